// round 3
// baseline (speedup 1.0000x reference)
#include <cuda_runtime.h>
#include <math.h>

#define NB    512            // batch
#define DF    256            // f feature dim
#define DZTOT 512            // STEP*DZ = 16*32
#define KF    (2*DF)         // 512  (concat [s^2, s])
#define KZ    (2*DZTOT)      // 1024
#define LOG_2PI 1.8378770664093453f

// ---------------- scratch (no allocations allowed) ----------------
__device__ float g_Xf[NB*KF];
__device__ float g_Wf[NB*KF];
__device__ float g_Af[NB];
__device__ float g_Xz[NB*KZ];
__device__ float g_Wz[NB*KZ];
__device__ float g_Az[NB];
__device__ float g_Qf[NB*NB];
__device__ float g_Qz[NB*NB];
__device__ float g_lse[3*NB];

// ---------------- 1) factorize params ----------------
// log_q[i,j] = A_j - 0.5*sum_d s_id^2*iv_jd + sum_d s_id*(m_jd*iv_jd)
//   A_j = -0.5*(D*LOG2PI + sum lv_j + sum m_j^2*iv_j)
__global__ void prep_kernel(const float* __restrict__ f_mean,
                            const float* __restrict__ f_logvar,
                            const float* __restrict__ f_sample,
                            const float* __restrict__ z_mean,
                            const float* __restrict__ z_logvar,
                            const float* __restrict__ z_sample) {
    int j = blockIdx.x;
    int t = threadIdx.x;          // 256 threads
    __shared__ float red[256];
    float part = 0.f;
    if (blockIdx.y == 0) {
        float lv = f_logvar[j*DF + t];
        float m  = f_mean  [j*DF + t];
        float s  = f_sample[j*DF + t];
        float iv = expf(-lv);
        g_Xf[j*KF + t]      = s*s;
        g_Xf[j*KF + DF + t] = s;
        g_Wf[j*KF + t]      = -0.5f*iv;
        g_Wf[j*KF + DF + t] = m*iv;
        part = lv + m*m*iv;
    } else {
        #pragma unroll
        for (int d = t; d < DZTOT; d += 256) {
            float lv = z_logvar[j*DZTOT + d];
            float m  = z_mean  [j*DZTOT + d];
            float s  = z_sample[j*DZTOT + d];
            float iv = expf(-lv);
            g_Xz[j*KZ + d]         = s*s;
            g_Xz[j*KZ + DZTOT + d] = s;
            g_Wz[j*KZ + d]         = -0.5f*iv;
            g_Wz[j*KZ + DZTOT + d] = m*iv;
            part += lv + m*m*iv;
        }
    }
    red[t] = part;
    __syncthreads();
    for (int off = 128; off > 0; off >>= 1) {
        if (t < off) red[t] += red[t+off];
        __syncthreads();
    }
    if (t == 0) {
        float D = (blockIdx.y == 0) ? (float)DF : (float)DZTOT;
        float A = -0.5f*(D*LOG_2PI + red[0]);
        if (blockIdx.y == 0) g_Af[j] = A; else g_Az[j] = A;
    }
}

// ---------------- 2) pairwise NT-GEMM: Q[i,j] = A_j + dot(X_i, W_j) ----------------
// BM=BN=64, BK=16, 256 threads, 4x4 microtile per thread
template<bool ISZ>
__global__ void pair_gemm_kernel() {
    constexpr int K = ISZ ? KZ : KF;
    const float* __restrict__ X = ISZ ? g_Xz : g_Xf;
    const float* __restrict__ W = ISZ ? g_Wz : g_Wf;
    const float* __restrict__ A = ISZ ? g_Az : g_Af;
    float* __restrict__ Q       = ISZ ? g_Qz : g_Qf;

    __shared__ __align__(16) float Xs[16][64];
    __shared__ __align__(16) float Ws[16][64];

    int t  = threadIdx.x;
    int tr = t >> 4;              // 0..15
    int tc = t & 15;              // 0..15
    int rowBase = blockIdx.y * 64;
    int colBase = blockIdx.x * 64;

    int lr = t >> 2;              // 0..63 row within tile for the load
    int lc = (t & 3) * 4;         // 0,4,8,12

    float acc[4][4] = {};

    for (int k0 = 0; k0 < K; k0 += 16) {
        float4 xa = *(const float4*)&X[(rowBase + lr)*K + k0 + lc];
        float4 wa = *(const float4*)&W[(colBase + lr)*K + k0 + lc];
        Xs[lc+0][lr] = xa.x; Xs[lc+1][lr] = xa.y; Xs[lc+2][lr] = xa.z; Xs[lc+3][lr] = xa.w;
        Ws[lc+0][lr] = wa.x; Ws[lc+1][lr] = wa.y; Ws[lc+2][lr] = wa.z; Ws[lc+3][lr] = wa.w;
        __syncthreads();
        #pragma unroll
        for (int kk = 0; kk < 16; kk++) {
            float4 a = *(const float4*)&Xs[kk][tr*4];
            float4 b = *(const float4*)&Ws[kk][tc*4];
            float am[4] = {a.x, a.y, a.z, a.w};
            float bn[4] = {b.x, b.y, b.z, b.w};
            #pragma unroll
            for (int m = 0; m < 4; m++)
                #pragma unroll
                for (int n = 0; n < 4; n++)
                    acc[m][n] += am[m]*bn[n];
        }
        __syncthreads();
    }

    #pragma unroll
    for (int m = 0; m < 4; m++) {
        int i = rowBase + tr*4 + m;
        #pragma unroll
        for (int n = 0; n < 4; n++) {
            int jj = colBase + tc*4 + n;
            Q[i*NB + jj] = acc[m][n] + A[jj];
        }
    }
}

// ---------------- 3) per-row logsumexp of Qf, Qz, Qf+Qz ----------------
__device__ __forceinline__ float block_max(float v, float* red, int t) {
    red[t] = v; __syncthreads();
    for (int off = 128; off > 0; off >>= 1) {
        if (t < off) red[t] = fmaxf(red[t], red[t+off]);
        __syncthreads();
    }
    float r = red[0]; __syncthreads();
    return r;
}
__device__ __forceinline__ float block_sum(float v, float* red, int t) {
    red[t] = v; __syncthreads();
    for (int off = 128; off > 0; off >>= 1) {
        if (t < off) red[t] += red[t+off];
        __syncthreads();
    }
    float r = red[0]; __syncthreads();
    return r;
}

__global__ void lse_kernel() {
    int i = blockIdx.x;
    int t = threadIdx.x;          // 256 threads, 2 cols each
    __shared__ float red[256];

    float a0 = g_Qf[i*NB + t], a1 = g_Qf[i*NB + t + 256];
    float b0 = g_Qz[i*NB + t], b1 = g_Qz[i*NB + t + 256];
    float c0 = a0 + b0,        c1 = a1 + b1;

    float Ma = block_max(fmaxf(a0, a1), red, t);
    float Mb = block_max(fmaxf(b0, b1), red, t);
    float Mc = block_max(fmaxf(c0, c1), red, t);

    float Sa = block_sum(expf(a0 - Ma) + expf(a1 - Ma), red, t);
    float Sb = block_sum(expf(b0 - Mb) + expf(b1 - Mb), red, t);
    float Sc = block_sum(expf(c0 - Mc) + expf(c1 - Mc), red, t);

    if (t == 0) {
        g_lse[0*NB + i] = Ma + logf(Sa);
        g_lse[1*NB + i] = Mb + logf(Sb);
        g_lse[2*NB + i] = Mc + logf(Sc);
    }
}

// ---------------- 4) final reduction -> [MI, Hf, Hz, Hfz] ----------------
__global__ void final_kernel(const int* __restrict__ num_train_p,
                             float* __restrict__ out, int out_size) {
    int t = threadIdx.x;          // 512 threads
    __shared__ float red[512];

    float vf  = g_lse[0*NB + t];
    float vz  = g_lse[1*NB + t];
    float vfz = g_lse[2*NB + t];

    float sums[3];
    float vals[3] = {vf, vz, vfz};
    #pragma unroll
    for (int q = 0; q < 3; q++) {
        red[t] = vals[q]; __syncthreads();
        for (int off = 256; off > 0; off >>= 1) {
            if (t < off) red[t] += red[t+off];
            __syncthreads();
        }
        sums[q] = red[0]; __syncthreads();
    }

    if (t == 0) {
        int v = num_train_p[0];
        float nt;
        if (v > 0 && v < (1 << 30)) nt = (float)v;          // int32 / int64-LE low word
        else nt = __int_as_float(v);                        // stored as float32
        float clogNM = logf(nt * (float)NB);
        float Hf  = -sums[0] / (float)NB + clogNM;
        float Hz  = -sums[1] / (float)NB + clogNM;
        float Hfz = -sums[2] / (float)NB + clogNM;
        float MI  = Hf + Hz - Hfz;
        if (out_size > 0) out[0] = MI;
        if (out_size > 1) out[1] = Hf;
        if (out_size > 2) out[2] = Hz;
        if (out_size > 3) out[3] = Hfz;
    }
}

// ---------------- launch ----------------
extern "C" void kernel_launch(void* const* d_in, const int* in_sizes, int n_in,
                              void* d_out, int out_size) {
    const float* f_mean   = (const float*)d_in[0];
    const float* f_logvar = (const float*)d_in[1];
    const float* f_sample = (const float*)d_in[2];
    const float* z_mean   = (const float*)d_in[3];
    const float* z_logvar = (const float*)d_in[4];
    const float* z_sample = (const float*)d_in[5];
    const int*   num_train = (const int*)d_in[6];

    prep_kernel<<<dim3(NB, 2), 256>>>(f_mean, f_logvar, f_sample,
                                      z_mean, z_logvar, z_sample);
    pair_gemm_kernel<false><<<dim3(8, 8), 256>>>();
    pair_gemm_kernel<true ><<<dim3(8, 8), 256>>>();
    lse_kernel<<<NB, 256>>>();
    final_kernel<<<1, 512>>>(num_train, (float*)d_out, out_size);
}

// round 4
// speedup vs baseline: 2.2338x; 2.2338x over previous
#include <cuda_runtime.h>
#include <math.h>

#define NB    512            // batch
#define DF    256            // f feature dim
#define DZTOT 512            // STEP*DZ = 16*32
#define KF    (2*DF)         // 512  (concat [s^2, s])
#define KZ    (2*DZTOT)      // 1024
#define SPLITF 2             // K-split for f  (chunk 256)
#define SPLITZ 4             // K-split for z  (chunk 256)
#define KCHUNK 256
#define LOG_2PI 1.8378770664093453f

// ---------------- scratch (no allocations allowed) ----------------
__device__ float g_Xf[NB*KF];
__device__ float g_Wf[NB*KF];
__device__ float g_Af[NB];
__device__ float g_Xz[NB*KZ];
__device__ float g_Wz[NB*KZ];
__device__ float g_Az[NB];
__device__ float g_Pf[SPLITF*NB*NB];   // split-K partials for Qf
__device__ float g_Pz[SPLITZ*NB*NB];   // split-K partials for Qz
__device__ float g_lse[3*NB];

// ---------------- 1) factorize params ----------------
// log_q[i,j] = A_j - 0.5*sum_d s_id^2*iv_jd + sum_d s_id*(m_jd*iv_jd)
//   A_j = -0.5*(D*LOG2PI + sum lv_j + sum m_j^2*iv_j)
__global__ void prep_kernel(const float* __restrict__ f_mean,
                            const float* __restrict__ f_logvar,
                            const float* __restrict__ f_sample,
                            const float* __restrict__ z_mean,
                            const float* __restrict__ z_logvar,
                            const float* __restrict__ z_sample) {
    int j = blockIdx.x;
    int t = threadIdx.x;          // 256 threads
    __shared__ float red[256];
    float part = 0.f;
    if (blockIdx.y == 0) {
        float lv = f_logvar[j*DF + t];
        float m  = f_mean  [j*DF + t];
        float s  = f_sample[j*DF + t];
        float iv = expf(-lv);
        g_Xf[j*KF + t]      = s*s;
        g_Xf[j*KF + DF + t] = s;
        g_Wf[j*KF + t]      = -0.5f*iv;
        g_Wf[j*KF + DF + t] = m*iv;
        part = lv + m*m*iv;
    } else {
        #pragma unroll
        for (int d = t; d < DZTOT; d += 256) {
            float lv = z_logvar[j*DZTOT + d];
            float m  = z_mean  [j*DZTOT + d];
            float s  = z_sample[j*DZTOT + d];
            float iv = expf(-lv);
            g_Xz[j*KZ + d]         = s*s;
            g_Xz[j*KZ + DZTOT + d] = s;
            g_Wz[j*KZ + d]         = -0.5f*iv;
            g_Wz[j*KZ + DZTOT + d] = m*iv;
            part += lv + m*m*iv;
        }
    }
    red[t] = part;
    __syncthreads();
    for (int off = 128; off > 0; off >>= 1) {
        if (t < off) red[t] += red[t+off];
        __syncthreads();
    }
    if (t == 0) {
        float D = (blockIdx.y == 0) ? (float)DF : (float)DZTOT;
        float A = -0.5f*(D*LOG_2PI + red[0]);
        if (blockIdx.y == 0) g_Af[j] = A; else g_Az[j] = A;
    }
}

// ---------------- 2) fused pairwise NT-GEMM (both matrices, split-K) ----------
// One launch; 384 equal blocks of 64x64x256. Blocks [0,128): f, [128,384): z.
// P[i,j] += dot(X_i[kOff:kOff+256], W_j[kOff:kOff+256]); A_j folded in later.
__global__ void __launch_bounds__(256, 4) gemm_kernel() {
    __shared__ __align__(16) float Xs[16][64];
    __shared__ __align__(16) float Ws[16][64];

    int b = blockIdx.x;
    const float* __restrict__ X;
    const float* __restrict__ W;
    float* __restrict__ P;
    int K, kOff, tileId;
    if (b < SPLITF*64) {
        int s = b >> 6; tileId = b & 63;
        X = g_Xf; W = g_Wf; P = g_Pf + s*(NB*NB); K = KF; kOff = s*KCHUNK;
    } else {
        b -= SPLITF*64;
        int s = b >> 6; tileId = b & 63;
        X = g_Xz; W = g_Wz; P = g_Pz + s*(NB*NB); K = KZ; kOff = s*KCHUNK;
    }
    int rowBase = (tileId >> 3) * 64;
    int colBase = (tileId & 7) * 64;

    int t  = threadIdx.x;
    int tr = t >> 4;              // 0..15
    int tc = t & 15;              // 0..15
    int lr = t >> 2;              // 0..63 (row within tile for loads)
    int lc = (t & 3) * 4;         // 0,4,8,12

    const float* xldg = &X[(rowBase + lr)*K + kOff + lc];
    const float* wldg = &W[(colBase + lr)*K + kOff + lc];

    float acc[4][4] = {};

    #pragma unroll 1
    for (int k0 = 0; k0 < KCHUNK; k0 += 16) {
        float4 xa = *(const float4*)(xldg + k0);
        float4 wa = *(const float4*)(wldg + k0);
        Xs[lc+0][lr] = xa.x; Xs[lc+1][lr] = xa.y; Xs[lc+2][lr] = xa.z; Xs[lc+3][lr] = xa.w;
        Ws[lc+0][lr] = wa.x; Ws[lc+1][lr] = wa.y; Ws[lc+2][lr] = wa.z; Ws[lc+3][lr] = wa.w;
        __syncthreads();
        #pragma unroll
        for (int kk = 0; kk < 16; kk++) {
            float4 a = *(const float4*)&Xs[kk][tr*4];
            float4 bq = *(const float4*)&Ws[kk][tc*4];
            float am[4] = {a.x, a.y, a.z, a.w};
            float bn[4] = {bq.x, bq.y, bq.z, bq.w};
            #pragma unroll
            for (int m = 0; m < 4; m++)
                #pragma unroll
                for (int n = 0; n < 4; n++)
                    acc[m][n] += am[m]*bn[n];
        }
        __syncthreads();
    }

    #pragma unroll
    for (int m = 0; m < 4; m++) {
        int i = rowBase + tr*4 + m;
        float4 v = make_float4(acc[m][0], acc[m][1], acc[m][2], acc[m][3]);
        *(float4*)&P[i*NB + colBase + tc*4] = v;
    }
}

// ---------------- 3) per-row logsumexp of Qf, Qz, Qf+Qz ------------------
// One block per row (128 threads, float4 per thread). Sums split-K partials
// and folds in A_j here.
__device__ __forceinline__ float bred_max(float v, float* sm, int t) {
    #pragma unroll
    for (int o = 16; o; o >>= 1) v = fmaxf(v, __shfl_xor_sync(0xffffffffu, v, o));
    if ((t & 31) == 0) sm[t >> 5] = v;
    __syncthreads();
    v = fmaxf(fmaxf(sm[0], sm[1]), fmaxf(sm[2], sm[3]));
    __syncthreads();
    return v;
}
__device__ __forceinline__ float bred_sum(float v, float* sm, int t) {
    #pragma unroll
    for (int o = 16; o; o >>= 1) v += __shfl_xor_sync(0xffffffffu, v, o);
    if ((t & 31) == 0) sm[t >> 5] = v;
    __syncthreads();
    v = (sm[0] + sm[1]) + (sm[2] + sm[3]);
    __syncthreads();
    return v;
}

__global__ void lse_kernel() {
    int i = blockIdx.x;
    int t = threadIdx.x;          // 128 threads, 4 cols each
    int j4 = t * 4;
    __shared__ float sm[4];

    const float4* pf0 = (const float4*)&g_Pf[0*(NB*NB) + i*NB + j4];
    const float4* pf1 = (const float4*)&g_Pf[1*(NB*NB) + i*NB + j4];
    float4 f0 = *pf0, f1 = *pf1;
    float4 qf = make_float4(f0.x+f1.x, f0.y+f1.y, f0.z+f1.z, f0.w+f1.w);

    float4 z0 = *(const float4*)&g_Pz[0*(NB*NB) + i*NB + j4];
    float4 z1 = *(const float4*)&g_Pz[1*(NB*NB) + i*NB + j4];
    float4 z2 = *(const float4*)&g_Pz[2*(NB*NB) + i*NB + j4];
    float4 z3 = *(const float4*)&g_Pz[3*(NB*NB) + i*NB + j4];
    float4 qz = make_float4((z0.x+z1.x)+(z2.x+z3.x), (z0.y+z1.y)+(z2.y+z3.y),
                            (z0.z+z1.z)+(z2.z+z3.z), (z0.w+z1.w)+(z2.w+z3.w));

    float4 af = *(const float4*)&g_Af[j4];
    float4 az = *(const float4*)&g_Az[j4];

    float a[4]  = {qf.x+af.x, qf.y+af.y, qf.z+af.z, qf.w+af.w};
    float bb[4] = {qz.x+az.x, qz.y+az.y, qz.z+az.z, qz.w+az.w};
    float c[4]  = {a[0]+bb[0], a[1]+bb[1], a[2]+bb[2], a[3]+bb[3]};

    float ma = fmaxf(fmaxf(a[0], a[1]), fmaxf(a[2], a[3]));
    float mb = fmaxf(fmaxf(bb[0], bb[1]), fmaxf(bb[2], bb[3]));
    float mc = fmaxf(fmaxf(c[0], c[1]), fmaxf(c[2], c[3]));

    float Ma = bred_max(ma, sm, t);
    float Mb = bred_max(mb, sm, t);
    float Mc = bred_max(mc, sm, t);

    float sa = (expf(a[0]-Ma)  + expf(a[1]-Ma))  + (expf(a[2]-Ma)  + expf(a[3]-Ma));
    float sb = (expf(bb[0]-Mb) + expf(bb[1]-Mb)) + (expf(bb[2]-Mb) + expf(bb[3]-Mb));
    float sc = (expf(c[0]-Mc)  + expf(c[1]-Mc))  + (expf(c[2]-Mc)  + expf(c[3]-Mc));

    float Sa = bred_sum(sa, sm, t);
    float Sb = bred_sum(sb, sm, t);
    float Sc = bred_sum(sc, sm, t);

    if (t == 0) {
        g_lse[0*NB + i] = Ma + logf(Sa);
        g_lse[1*NB + i] = Mb + logf(Sb);
        g_lse[2*NB + i] = Mc + logf(Sc);
    }
}

// ---------------- 4) final reduction -> [MI, Hf, Hz, Hfz] ----------------
__global__ void final_kernel(const int* __restrict__ num_train_p,
                             float* __restrict__ out, int out_size) {
    int t = threadIdx.x;          // 512 threads
    __shared__ float red[512];

    float sums[3];
    #pragma unroll
    for (int q = 0; q < 3; q++) {
        red[t] = g_lse[q*NB + t]; __syncthreads();
        for (int off = 256; off > 0; off >>= 1) {
            if (t < off) red[t] += red[t+off];
            __syncthreads();
        }
        sums[q] = red[0]; __syncthreads();
    }

    if (t == 0) {
        int v = num_train_p[0];
        float nt;
        if (v > 0 && v < (1 << 30)) nt = (float)v;          // int32 / int64-LE low word
        else nt = __int_as_float(v);                        // stored as float32
        float clogNM = logf(nt * (float)NB);
        float Hf  = -sums[0] / (float)NB + clogNM;
        float Hz  = -sums[1] / (float)NB + clogNM;
        float Hfz = -sums[2] / (float)NB + clogNM;
        float MI  = Hf + Hz - Hfz;
        if (out_size > 0) out[0] = MI;
        if (out_size > 1) out[1] = Hf;
        if (out_size > 2) out[2] = Hz;
        if (out_size > 3) out[3] = Hfz;
    }
}

// ---------------- launch ----------------
extern "C" void kernel_launch(void* const* d_in, const int* in_sizes, int n_in,
                              void* d_out, int out_size) {
    const float* f_mean   = (const float*)d_in[0];
    const float* f_logvar = (const float*)d_in[1];
    const float* f_sample = (const float*)d_in[2];
    const float* z_mean   = (const float*)d_in[3];
    const float* z_logvar = (const float*)d_in[4];
    const float* z_sample = (const float*)d_in[5];
    const int*   num_train = (const int*)d_in[6];

    prep_kernel<<<dim3(NB, 2), 256>>>(f_mean, f_logvar, f_sample,
                                      z_mean, z_logvar, z_sample);
    gemm_kernel<<<(SPLITF + SPLITZ) * 64, 256>>>();
    lse_kernel<<<NB, 128>>>();
    final_kernel<<<1, 512>>>(num_train, (float*)d_out, out_size);
}

// round 5
// speedup vs baseline: 2.3145x; 1.0362x over previous
#include <cuda_runtime.h>
#include <math.h>

#define NB    512            // batch
#define DF    256            // f feature dim
#define DZTOT 512            // STEP*DZ = 16*32
#define KF    (2*DF)         // 512  (concat [s^2, s])
#define KZ    (2*DZTOT)      // 1024
#define BM    128
#define BN    64
#define BK    16
#define KCH   128            // K chunk per block
#define SPLITF 4             // 512/128
#define SPLITZ 8             // 1024/128
#define LOG_2PI 1.8378770664093453f

// ---------------- scratch (no allocations allowed) ----------------
__device__ float g_Xf[NB*KF];
__device__ float g_Wf[NB*KF];
__device__ float g_Af[NB];
__device__ float g_Xz[NB*KZ];
__device__ float g_Wz[NB*KZ];
__device__ float g_Az[NB];
__device__ float g_Pf[SPLITF*NB*NB];   // split-K partials for Qf
__device__ float g_Pz[SPLITZ*NB*NB];   // split-K partials for Qz
__device__ float g_lse[3*NB];
__device__ int   g_ctr;                // last-block ticket (self-resetting)

// ---------------- 1) factorize params ----------------
// log_q[i,j] = A_j - 0.5*sum_d s_id^2*iv_jd + sum_d s_id*(m_jd*iv_jd)
__global__ void prep_kernel(const float* __restrict__ f_mean,
                            const float* __restrict__ f_logvar,
                            const float* __restrict__ f_sample,
                            const float* __restrict__ z_mean,
                            const float* __restrict__ z_logvar,
                            const float* __restrict__ z_sample) {
    int j = blockIdx.x;
    int t = threadIdx.x;          // 256 threads
    __shared__ float red[256];
    float part = 0.f;
    if (blockIdx.y == 0) {
        float lv = f_logvar[j*DF + t];
        float m  = f_mean  [j*DF + t];
        float s  = f_sample[j*DF + t];
        float iv = expf(-lv);
        g_Xf[j*KF + t]      = s*s;
        g_Xf[j*KF + DF + t] = s;
        g_Wf[j*KF + t]      = -0.5f*iv;
        g_Wf[j*KF + DF + t] = m*iv;
        part = lv + m*m*iv;
    } else {
        #pragma unroll
        for (int d = t; d < DZTOT; d += 256) {
            float lv = z_logvar[j*DZTOT + d];
            float m  = z_mean  [j*DZTOT + d];
            float s  = z_sample[j*DZTOT + d];
            float iv = expf(-lv);
            g_Xz[j*KZ + d]         = s*s;
            g_Xz[j*KZ + DZTOT + d] = s;
            g_Wz[j*KZ + d]         = -0.5f*iv;
            g_Wz[j*KZ + DZTOT + d] = m*iv;
            part += lv + m*m*iv;
        }
    }
    red[t] = part;
    __syncthreads();
    for (int off = 128; off > 0; off >>= 1) {
        if (t < off) red[t] += red[t+off];
        __syncthreads();
    }
    if (t == 0) {
        float D = (blockIdx.y == 0) ? (float)DF : (float)DZTOT;
        float A = -0.5f*(D*LOG_2PI + red[0]);
        if (blockIdx.y == 0) g_Af[j] = A; else g_Az[j] = A;
    }
}

// ---------------- 2) fused pairwise NT-GEMM, packed f32x2 ---------------
// 384 blocks of BMxBNxKCH = 128x64x128. Blocks [0,128): f, [128,384): z.
// Accumulators are fp32 pairs packed over adjacent M rows (fma.rn.f32x2).
__device__ __forceinline__ void fma2(unsigned long long &d,
                                     unsigned long long a,
                                     unsigned long long b) {
    asm("fma.rn.f32x2 %0, %1, %2, %0;" : "+l"(d) : "l"(a), "l"(b));
}

__global__ void __launch_bounds__(256, 2) gemm_kernel() {
    __shared__ __align__(16) float  Xs[BK][130];     // [kk][m], pad->conflict-free fill
    __shared__ __align__(16) float2 Ws2[BK][65];     // [kk][pos], value duplicated {w,w}

    int b = blockIdx.x;
    const float* __restrict__ X;
    const float* __restrict__ W;
    float* __restrict__ P;
    int K, kOff, tile;
    if (b < SPLITF*32) {
        int s = b >> 5; tile = b & 31;
        X = g_Xf; W = g_Wf; P = g_Pf + s*(NB*NB); K = KF; kOff = s*KCH;
    } else {
        b -= SPLITF*32;
        int s = b >> 5; tile = b & 31;
        X = g_Xz; W = g_Wz; P = g_Pz + s*(NB*NB); K = KZ; kOff = s*KCH;
    }
    int rowBase = (tile >> 3) * BM;
    int colBase = (tile & 7) * BN;

    int t  = threadIdx.x;
    int tr = t >> 4;              // 0..15 -> m base = tr*8
    int tc = t & 15;              // 0..15 -> n base = tc*4
    int lr = t >> 2;              // 0..63 load row
    int ls = (t & 3) * 4;         // k seg 0,4,8,12

    const float* xg  = &X[(rowBase + lr)*K + kOff + ls];
    const float* xg2 = xg + 64*K;
    const float* wg  = &W[(colBase + lr)*K + kOff + ls];
    int wpos = ((lr & 3) << 4) + (lr >> 2);   // store col n=lr at pos (n&3)*16+(n>>2)

    unsigned long long acc[4][4] = {};

    #pragma unroll 1
    for (int k0 = 0; k0 < KCH; k0 += BK) {
        float4 xa = *(const float4*)(xg  + k0);
        float4 xb = *(const float4*)(xg2 + k0);
        float4 wv = *(const float4*)(wg  + k0);
        Xs[ls+0][lr]    = xa.x; Xs[ls+1][lr]    = xa.y; Xs[ls+2][lr]    = xa.z; Xs[ls+3][lr]    = xa.w;
        Xs[ls+0][lr+64] = xb.x; Xs[ls+1][lr+64] = xb.y; Xs[ls+2][lr+64] = xb.z; Xs[ls+3][lr+64] = xb.w;
        Ws2[ls+0][wpos] = make_float2(wv.x, wv.x);
        Ws2[ls+1][wpos] = make_float2(wv.y, wv.y);
        Ws2[ls+2][wpos] = make_float2(wv.z, wv.z);
        Ws2[ls+3][wpos] = make_float2(wv.w, wv.w);
        __syncthreads();
        #pragma unroll
        for (int kk = 0; kk < BK; kk++) {
            unsigned long long a2[4], b2[4];
            #pragma unroll
            for (int p = 0; p < 4; p++)
                a2[p] = *(const unsigned long long*)&Xs[kk][tr*8 + 2*p];
            #pragma unroll
            for (int n = 0; n < 4; n++)
                b2[n] = *(const unsigned long long*)&Ws2[kk][(n << 4) + tc];
            #pragma unroll
            for (int p = 0; p < 4; p++)
                #pragma unroll
                for (int n = 0; n < 4; n++)
                    fma2(acc[p][n], a2[p], b2[n]);
        }
        __syncthreads();
    }

    #pragma unroll
    for (int p = 0; p < 4; p++) {
        float2 c0 = *(float2*)&acc[p][0];
        float2 c1 = *(float2*)&acc[p][1];
        float2 c2 = *(float2*)&acc[p][2];
        float2 c3 = *(float2*)&acc[p][3];
        int r0 = rowBase + tr*8 + 2*p;
        *(float4*)&P[ r0   *NB + colBase + tc*4] = make_float4(c0.x, c1.x, c2.x, c3.x);
        *(float4*)&P[(r0+1)*NB + colBase + tc*4] = make_float4(c0.y, c1.y, c2.y, c3.y);
    }
}

// ---------------- 3) per-row LSE + fused final reduction -----------------
__device__ __forceinline__ float bred_max(float v, float* sm, int t) {
    #pragma unroll
    for (int o = 16; o; o >>= 1) v = fmaxf(v, __shfl_xor_sync(0xffffffffu, v, o));
    if ((t & 31) == 0) sm[t >> 5] = v;
    __syncthreads();
    v = fmaxf(fmaxf(sm[0], sm[1]), fmaxf(sm[2], sm[3]));
    __syncthreads();
    return v;
}
__device__ __forceinline__ float bred_sum(float v, float* sm, int t) {
    #pragma unroll
    for (int o = 16; o; o >>= 1) v += __shfl_xor_sync(0xffffffffu, v, o);
    if ((t & 31) == 0) sm[t >> 5] = v;
    __syncthreads();
    v = (sm[0] + sm[1]) + (sm[2] + sm[3]);
    __syncthreads();
    return v;
}

__global__ void lse_kernel(const int* __restrict__ num_train_p,
                           float* __restrict__ out, int out_size) {
    int i = blockIdx.x;
    int t = threadIdx.x;          // 128 threads, 4 cols each
    int j4 = t * 4;
    __shared__ float sm[4];
    __shared__ bool isLast;

    float a[4]  = {0.f, 0.f, 0.f, 0.f};
    float bb[4] = {0.f, 0.f, 0.f, 0.f};
    #pragma unroll
    for (int s = 0; s < SPLITF; s++) {
        float4 v = *(const float4*)&g_Pf[s*(NB*NB) + i*NB + j4];
        a[0] += v.x; a[1] += v.y; a[2] += v.z; a[3] += v.w;
    }
    #pragma unroll
    for (int s = 0; s < SPLITZ; s++) {
        float4 v = *(const float4*)&g_Pz[s*(NB*NB) + i*NB + j4];
        bb[0] += v.x; bb[1] += v.y; bb[2] += v.z; bb[3] += v.w;
    }
    float4 af = *(const float4*)&g_Af[j4];
    float4 az = *(const float4*)&g_Az[j4];
    a[0] += af.x; a[1] += af.y; a[2] += af.z; a[3] += af.w;
    bb[0] += az.x; bb[1] += az.y; bb[2] += az.z; bb[3] += az.w;
    float c[4] = {a[0]+bb[0], a[1]+bb[1], a[2]+bb[2], a[3]+bb[3]};

    float Ma = bred_max(fmaxf(fmaxf(a[0], a[1]),  fmaxf(a[2], a[3])),  sm, t);
    float Mb = bred_max(fmaxf(fmaxf(bb[0], bb[1]), fmaxf(bb[2], bb[3])), sm, t);
    float Mc = bred_max(fmaxf(fmaxf(c[0], c[1]),  fmaxf(c[2], c[3])),  sm, t);

    float Sa = bred_sum((expf(a[0]-Ma)  + expf(a[1]-Ma))  + (expf(a[2]-Ma)  + expf(a[3]-Ma)),  sm, t);
    float Sb = bred_sum((expf(bb[0]-Mb) + expf(bb[1]-Mb)) + (expf(bb[2]-Mb) + expf(bb[3]-Mb)), sm, t);
    float Sc = bred_sum((expf(c[0]-Mc)  + expf(c[1]-Mc))  + (expf(c[2]-Mc)  + expf(c[3]-Mc)),  sm, t);

    if (t == 0) {
        g_lse[0*NB + i] = Ma + logf(Sa);
        g_lse[1*NB + i] = Mb + logf(Sb);
        g_lse[2*NB + i] = Mc + logf(Sc);
        __threadfence();                       // publish before ticket
        int v = atomicAdd(&g_ctr, 1);
        isLast = (v == NB - 1);
    }
    __syncthreads();

    if (isLast) {                              // uniform within the block
        float s0 = 0.f, s1 = 0.f, s2 = 0.f;
        #pragma unroll
        for (int r = t; r < NB; r += 128) {
            s0 += g_lse[0*NB + r];
            s1 += g_lse[1*NB + r];
            s2 += g_lse[2*NB + r];
        }
        s0 = bred_sum(s0, sm, t);
        s1 = bred_sum(s1, sm, t);
        s2 = bred_sum(s2, sm, t);
        if (t == 0) {
            g_ctr = 0;                         // reset for next graph replay
            int v = num_train_p[0];
            float nt;
            if (v > 0 && v < (1 << 30)) nt = (float)v;   // int32 path
            else nt = __int_as_float(v);                 // stored-as-float path
            float clogNM = logf(nt * (float)NB);
            float Hf  = -s0 / (float)NB + clogNM;
            float Hz  = -s1 / (float)NB + clogNM;
            float Hfz = -s2 / (float)NB + clogNM;
            float MI  = Hf + Hz - Hfz;
            if (out_size > 0) out[0] = MI;
            if (out_size > 1) out[1] = Hf;
            if (out_size > 2) out[2] = Hz;
            if (out_size > 3) out[3] = Hfz;
        }
    }
}

// ---------------- launch ----------------
extern "C" void kernel_launch(void* const* d_in, const int* in_sizes, int n_in,
                              void* d_out, int out_size) {
    const float* f_mean   = (const float*)d_in[0];
    const float* f_logvar = (const float*)d_in[1];
    const float* f_sample = (const float*)d_in[2];
    const float* z_mean   = (const float*)d_in[3];
    const float* z_logvar = (const float*)d_in[4];
    const float* z_sample = (const float*)d_in[5];
    const int*   num_train = (const int*)d_in[6];

    prep_kernel<<<dim3(NB, 2), 256>>>(f_mean, f_logvar, f_sample,
                                      z_mean, z_logvar, z_sample);
    gemm_kernel<<<(SPLITF + SPLITZ) * 32, 256>>>();
    lse_kernel<<<NB, 128>>>(num_train, (float*)d_out, out_size);
}

// round 8
// speedup vs baseline: 2.4566x; 1.0614x over previous
#include <cuda_runtime.h>
#include <math.h>
#include <stdint.h>

#define NB    512
#define DF    256
#define DZTOT 512
#define KF    512            // 2*DF   (concat [s^2, s], k-interleaved)
#define KZ    1024           // 2*DZTOT
#define BM    128
#define BN    64
#define BK    32
#define NT    16             // 512 / 32 K-stages per CTA
#define SPLITZ 2
#define LOG_2PI 1.8378770664093453f

// smem stage layout (floats): Ahi[128][40], Alo, Bhi[64][40], Blo
#define ASTR  40
#define BSTR  40
#define A_BYTES (BM*ASTR*4)               // 20480
#define B_BYTES (BN*BSTR*4)               // 10240
#define ST_SIZE (2*A_BYTES + 2*B_BYTES)   // 61440
#define SMEM_DYN (2*ST_SIZE)              // 122880

// ---------------- scratch ----------------
__device__ float g_Xf[NB*KF];
__device__ float g_Wf[NB*KF];
__device__ float g_Af[NB];
__device__ float g_Xz[NB*KZ];
__device__ float g_Wz[NB*KZ];
__device__ float g_Az[NB];
__device__ float g_Pf[NB*NB];             // f result
__device__ float g_Pz[SPLITZ*NB*NB];      // z split-K partials
__device__ float g_lse[3*NB];
__device__ int   g_ctr;

__device__ __forceinline__ float tf32r(float x){
    uint32_t u; asm("cvt.rna.tf32.f32 %0, %1;" : "=r"(u) : "f"(x)); return __uint_as_float(u);
}
__device__ __forceinline__ void mma8(float* d, const uint32_t* a, const uint32_t* b){
    asm("mma.sync.aligned.m16n8k8.row.col.f32.tf32.tf32.f32 "
        "{%0,%1,%2,%3}, {%4,%5,%6,%7}, {%8,%9}, {%0,%1,%2,%3};"
        : "+f"(d[0]), "+f"(d[1]), "+f"(d[2]), "+f"(d[3])
        : "r"(a[0]), "r"(a[1]), "r"(a[2]), "r"(a[3]), "r"(b[0]), "r"(b[1]));
}

// k-interleave within each 8-group so fragment pairs (k, k+4) are adjacent
__device__ __forceinline__ int kperm(int k){
    return (k & ~7) | ((k & 3) << 1) | ((k >> 2) & 1);
}

// ---------------- 1) factorize params (k-permuted layout) ----------------
// log_q[i,j] = A_j + dot(X_i, W_j);  X=[s^2, s], W=[-0.5*iv, m*iv]
__global__ void prep_kernel(const float* __restrict__ f_mean,
                            const float* __restrict__ f_logvar,
                            const float* __restrict__ f_sample,
                            const float* __restrict__ z_mean,
                            const float* __restrict__ z_logvar,
                            const float* __restrict__ z_sample) {
    int j = blockIdx.x;
    int t = threadIdx.x;          // 256 threads
    __shared__ float red[256];
    float part = 0.f;
    if (blockIdx.y == 0) {
        float lv = f_logvar[j*DF + t];
        float m  = f_mean  [j*DF + t];
        float s  = f_sample[j*DF + t];
        float iv = expf(-lv);
        int kp = kperm(t);
        g_Xf[j*KF + kp]      = s*s;
        g_Xf[j*KF + DF + kp] = s;
        g_Wf[j*KF + kp]      = -0.5f*iv;
        g_Wf[j*KF + DF + kp] = m*iv;
        part = lv + m*m*iv;
    } else {
        #pragma unroll
        for (int d = t; d < DZTOT; d += 256) {
            float lv = z_logvar[j*DZTOT + d];
            float m  = z_mean  [j*DZTOT + d];
            float s  = z_sample[j*DZTOT + d];
            float iv = expf(-lv);
            int kp = kperm(d);
            g_Xz[j*KZ + kp]         = s*s;
            g_Xz[j*KZ + DZTOT + kp] = s;
            g_Wz[j*KZ + kp]         = -0.5f*iv;
            g_Wz[j*KZ + DZTOT + kp] = m*iv;
            part += lv + m*m*iv;
        }
    }
    red[t] = part;
    __syncthreads();
    for (int off = 128; off > 0; off >>= 1) {
        if (t < off) red[t] += red[t+off];
        __syncthreads();
    }
    if (t == 0) {
        float D = (blockIdx.y == 0) ? (float)DF : (float)DZTOT;
        float A = -0.5f*(D*LOG_2PI + red[0]);
        if (blockIdx.y == 0) g_Af[j] = A; else g_Az[j] = A;
    }
}

// ---------------- 2) mma.sync tf32 NT-GEMM with hi/lo compensation -------
// D[i,j] = sum_k X[i,k]*W[j,k]; D += Ahi*Bhi + Ahi*Blo + Alo*Bhi (fp32 acc).
__global__ void __launch_bounds__(256, 1) gemm_mma_kernel() {
    extern __shared__ float dsm[];

    int t    = threadIdx.x;
    int lane = t & 31;
    int wid  = t >> 5;
    int wm   = wid >> 1;          // 0..3 -> 32-row slab
    int wn   = wid & 1;           // 0..1 -> 32-col slab
    int g    = lane >> 2;         // groupID
    int c    = lane & 3;          // threadID_in_group

    // block mapping: [0,32) f ; [32,96) z with split-K 2
    int b = blockIdx.x;
    const float* __restrict__ X;
    const float* __restrict__ W;
    float* __restrict__ P;
    int K, kOff;
    if (b < 32) { X = g_Xf; W = g_Wf; P = g_Pf; K = KF; kOff = 0; }
    else { b -= 32; int s = b >> 5; b &= 31;
           X = g_Xz; W = g_Wz; P = g_Pz + s*(NB*NB); K = KZ; kOff = s*512; }
    int rowBase = (b >> 3) * BM;
    int colBase = (b & 7) * BN;

    const float* Xb = X + rowBase*K + kOff;
    const float* Wb = W + colBase*K + kOff;

    float4 pre[6];
    auto ldg = [&](int kt){
        int kb = kt*BK;
        #pragma unroll
        for (int i = 0; i < 4; i++) {          // A: 128 rows x 8 float4
            int idx = t + 256*i, r = idx >> 3, c4 = idx & 7;
            pre[i] = *(const float4*)&Xb[r*K + kb + c4*4];
        }
        #pragma unroll
        for (int i = 0; i < 2; i++) {          // B: 64 rows x 8 float4
            int idx = t + 256*i, r = idx >> 3, c4 = idx & 7;
            pre[4+i] = *(const float4*)&Wb[r*K + kb + c4*4];
        }
    };
    auto sts = [&](int s){
        char* st = (char*)dsm + s*ST_SIZE;
        #pragma unroll
        for (int i = 0; i < 4; i++) {
            int idx = t + 256*i, r = idx >> 3, c4 = idx & 7;
            float4 v = pre[i], h, l;
            h.x = tf32r(v.x); l.x = tf32r(v.x - h.x);
            h.y = tf32r(v.y); l.y = tf32r(v.y - h.y);
            h.z = tf32r(v.z); l.z = tf32r(v.z - h.z);
            h.w = tf32r(v.w); l.w = tf32r(v.w - h.w);
            int off = (r*ASTR + c4*4)*4;
            *(float4*)(st + off)           = h;
            *(float4*)(st + A_BYTES + off) = l;
        }
        #pragma unroll
        for (int i = 0; i < 2; i++) {
            int idx = t + 256*i, r = idx >> 3, c4 = idx & 7;
            float4 v = pre[4+i], h, l;
            h.x = tf32r(v.x); l.x = tf32r(v.x - h.x);
            h.y = tf32r(v.y); l.y = tf32r(v.y - h.y);
            h.z = tf32r(v.z); l.z = tf32r(v.z - h.z);
            h.w = tf32r(v.w); l.w = tf32r(v.w - h.w);
            int off = (r*BSTR + c4*4)*4;
            *(float4*)(st + 2*A_BYTES + off)           = h;
            *(float4*)(st + 2*A_BYTES + B_BYTES + off) = l;
        }
    };

    float acc[2][4][4] = {};

    auto compute = [&](int s){
        const char* st = (const char*)dsm + s*ST_SIZE;
        const float* Ah = (const float*)st;
        const float* Al = (const float*)(st + A_BYTES);
        const float* Bh = (const float*)(st + 2*A_BYTES);
        const float* Bl = (const float*)(st + 2*A_BYTES + B_BYTES);
        #pragma unroll
        for (int g8 = 0; g8 < 4; g8++) {
            int ko = g8*8 + 2*c;
            uint32_t ah[2][4], al[2][4], bh[4][2], bl[4][2];
            #pragma unroll
            for (int ma = 0; ma < 2; ma++) {
                int r0 = (wm*32 + ma*16 + g)*ASTR + ko;
                float2 p0 = *(const float2*)&Ah[r0];
                float2 p1 = *(const float2*)&Ah[r0 + 8*ASTR];
                ah[ma][0] = __float_as_uint(p0.x); ah[ma][1] = __float_as_uint(p1.x);
                ah[ma][2] = __float_as_uint(p0.y); ah[ma][3] = __float_as_uint(p1.y);
                float2 q0 = *(const float2*)&Al[r0];
                float2 q1 = *(const float2*)&Al[r0 + 8*ASTR];
                al[ma][0] = __float_as_uint(q0.x); al[ma][1] = __float_as_uint(q1.x);
                al[ma][2] = __float_as_uint(q0.y); al[ma][3] = __float_as_uint(q1.y);
            }
            #pragma unroll
            for (int nb = 0; nb < 4; nb++) {
                int r0 = (wn*32 + nb*8 + g)*BSTR + ko;
                float2 p = *(const float2*)&Bh[r0];
                bh[nb][0] = __float_as_uint(p.x); bh[nb][1] = __float_as_uint(p.y);
                float2 q = *(const float2*)&Bl[r0];
                bl[nb][0] = __float_as_uint(q.x); bl[nb][1] = __float_as_uint(q.y);
            }
            #pragma unroll
            for (int ma = 0; ma < 2; ma++)
                #pragma unroll
                for (int nb = 0; nb < 4; nb++) {
                    mma8(acc[ma][nb], ah[ma], bh[nb]);
                    mma8(acc[ma][nb], ah[ma], bl[nb]);
                    mma8(acc[ma][nb], al[ma], bh[nb]);
                }
        }
    };

    ldg(0); sts(0); __syncthreads();
    for (int kt = 0; kt < NT; kt++) {
        int s = kt & 1;
        if (kt + 1 < NT) ldg(kt + 1);
        compute(s);
        if (kt + 1 < NT) { sts(s ^ 1); __syncthreads(); }
    }

    // epilogue: c0,c1 at (row, 2c),(row, 2c+1); c2,c3 at row+8
    #pragma unroll
    for (int ma = 0; ma < 2; ma++) {
        int i0 = rowBase + wm*32 + ma*16 + g;
        #pragma unroll
        for (int nb = 0; nb < 4; nb++) {
            int j0 = colBase + wn*32 + nb*8 + 2*c;
            *(float2*)&P[ i0   *NB + j0] = make_float2(acc[ma][nb][0], acc[ma][nb][1]);
            *(float2*)&P[(i0+8)*NB + j0] = make_float2(acc[ma][nb][2], acc[ma][nb][3]);
        }
    }
}

// ---------------- 3) per-row LSE + fused final reduction -----------------
__device__ __forceinline__ float bred_max(float v, float* sm, int t) {
    #pragma unroll
    for (int o = 16; o; o >>= 1) v = fmaxf(v, __shfl_xor_sync(0xffffffffu, v, o));
    if ((t & 31) == 0) sm[t >> 5] = v;
    __syncthreads();
    v = fmaxf(fmaxf(sm[0], sm[1]), fmaxf(sm[2], sm[3]));
    __syncthreads();
    return v;
}
__device__ __forceinline__ float bred_sum(float v, float* sm, int t) {
    #pragma unroll
    for (int o = 16; o; o >>= 1) v += __shfl_xor_sync(0xffffffffu, v, o);
    if ((t & 31) == 0) sm[t >> 5] = v;
    __syncthreads();
    v = (sm[0] + sm[1]) + (sm[2] + sm[3]);
    __syncthreads();
    return v;
}

__global__ void lse_kernel(const int* __restrict__ num_train_p,
                           float* __restrict__ out, int out_size) {
    int i = blockIdx.x;
    int t = threadIdx.x;          // 128 threads, 4 cols each
    int j4 = t * 4;
    __shared__ float sm[4];
    __shared__ bool isLast;

    float4 qf = *(const float4*)&g_Pf[i*NB + j4];
    float4 z0 = *(const float4*)&g_Pz[0*(NB*NB) + i*NB + j4];
    float4 z1 = *(const float4*)&g_Pz[1*(NB*NB) + i*NB + j4];
    float4 af = *(const float4*)&g_Af[j4];
    float4 az = *(const float4*)&g_Az[j4];

    float a[4]  = {qf.x+af.x, qf.y+af.y, qf.z+af.z, qf.w+af.w};
    float bb[4] = {z0.x+z1.x+az.x, z0.y+z1.y+az.y, z0.z+z1.z+az.z, z0.w+z1.w+az.w};
    float cc[4] = {a[0]+bb[0], a[1]+bb[1], a[2]+bb[2], a[3]+bb[3]};

    float Ma = bred_max(fmaxf(fmaxf(a[0], a[1]),   fmaxf(a[2], a[3])),   sm, t);
    float Mb = bred_max(fmaxf(fmaxf(bb[0], bb[1]), fmaxf(bb[2], bb[3])), sm, t);
    float Mc = bred_max(fmaxf(fmaxf(cc[0], cc[1]), fmaxf(cc[2], cc[3])), sm, t);

    float Sa = bred_sum((expf(a[0]-Ma)  + expf(a[1]-Ma))  + (expf(a[2]-Ma)  + expf(a[3]-Ma)),  sm, t);
    float Sb = bred_sum((expf(bb[0]-Mb) + expf(bb[1]-Mb)) + (expf(bb[2]-Mb) + expf(bb[3]-Mb)), sm, t);
    float Sc = bred_sum((expf(cc[0]-Mc) + expf(cc[1]-Mc)) + (expf(cc[2]-Mc) + expf(cc[3]-Mc)), sm, t);

    if (t == 0) {
        g_lse[0*NB + i] = Ma + logf(Sa);
        g_lse[1*NB + i] = Mb + logf(Sb);
        g_lse[2*NB + i] = Mc + logf(Sc);
        __threadfence();
        int v = atomicAdd(&g_ctr, 1);
        isLast = (v == NB - 1);
    }
    __syncthreads();

    if (isLast) {
        float s0 = 0.f, s1 = 0.f, s2 = 0.f;
        #pragma unroll
        for (int r = t; r < NB; r += 128) {
            s0 += g_lse[0*NB + r];
            s1 += g_lse[1*NB + r];
            s2 += g_lse[2*NB + r];
        }
        s0 = bred_sum(s0, sm, t);
        s1 = bred_sum(s1, sm, t);
        s2 = bred_sum(s2, sm, t);
        if (t == 0) {
            g_ctr = 0;
            int v = num_train_p[0];
            float nt;
            if (v > 0 && v < (1 << 30)) nt = (float)v;
            else nt = __int_as_float(v);
            float clogNM = logf(nt * (float)NB);
            float Hf  = -s0 / (float)NB + clogNM;
            float Hz  = -s1 / (float)NB + clogNM;
            float Hfz = -s2 / (float)NB + clogNM;
            float MI  = Hf + Hz - Hfz;
            if (out_size > 0) out[0] = MI;
            if (out_size > 1) out[1] = Hf;
            if (out_size > 2) out[2] = Hz;
            if (out_size > 3) out[3] = Hfz;
        }
    }
}

// ---------------- launch ----------------
extern "C" void kernel_launch(void* const* d_in, const int* in_sizes, int n_in,
                              void* d_out, int out_size) {
    const float* f_mean   = (const float*)d_in[0];
    const float* f_logvar = (const float*)d_in[1];
    const float* f_sample = (const float*)d_in[2];
    const float* z_mean   = (const float*)d_in[3];
    const float* z_logvar = (const float*)d_in[4];
    const float* z_sample = (const float*)d_in[5];
    const int*   num_train = (const int*)d_in[6];

    static int smem_set = 0;
    if (!smem_set) {
        cudaFuncSetAttribute(gemm_mma_kernel,
                             cudaFuncAttributeMaxDynamicSharedMemorySize, SMEM_DYN);
        smem_set = 1;
    }

    prep_kernel<<<dim3(NB, 2), 256>>>(f_mean, f_logvar, f_sample,
                                      z_mean, z_logvar, z_sample);
    gemm_mma_kernel<<<96, 256, SMEM_DYN>>>();
    lse_kernel<<<NB, 128>>>(num_train, (float*)d_out, out_size);
}

// round 10
// speedup vs baseline: 2.7429x; 1.1165x over previous
#include <cuda_runtime.h>
#include <math.h>
#include <stdint.h>

#define NB    512
#define DF    256
#define DZTOT 512
#define KF    512            // 2*DF   (concat [s^2, s], k-interleaved)
#define KZ    1024           // 2*DZTOT
#define BM    128
#define BN    64
#define BK    16
#define NSTG  8              // BK16 stages per CTA (K-chunk 128)
#define KCH   128
#define SPLITF 4
#define SPLITZ 8
#define LOG_2PI 1.8378770664093453f

// smem stage layout (floats): Ahi[128][20], Alo, Bhi[64][20], Blo
#define ASTR  20
#define BSTR  20
#define A_BYTES (BM*ASTR*4)               // 10240
#define B_BYTES (BN*BSTR*4)               // 5120
#define ST_SIZE (2*A_BYTES + 2*B_BYTES)   // 30720
#define SMEM_DYN (2*ST_SIZE)              // 61440 -> 2 CTAs/SM

// ---------------- scratch ----------------
__device__ float g_Xf[NB*KF];
__device__ float g_Wf[NB*KF];
__device__ float g_Af[NB];
__device__ float g_Xz[NB*KZ];
__device__ float g_Wz[NB*KZ];
__device__ float g_Az[NB];
__device__ float g_Pf[SPLITF*NB*NB];
__device__ float g_Pz[SPLITZ*NB*NB];
__device__ float g_lse[3*NB];
__device__ int   g_ctr;

__device__ __forceinline__ float tf32r(float x){
    uint32_t u; asm("cvt.rna.tf32.f32 %0, %1;" : "=r"(u) : "f"(x)); return __uint_as_float(u);
}
__device__ __forceinline__ void mma8(float* d, const uint32_t* a, const uint32_t* b){
    asm("mma.sync.aligned.m16n8k8.row.col.f32.tf32.tf32.f32 "
        "{%0,%1,%2,%3}, {%4,%5,%6,%7}, {%8,%9}, {%0,%1,%2,%3};"
        : "+f"(d[0]), "+f"(d[1]), "+f"(d[2]), "+f"(d[3])
        : "r"(a[0]), "r"(a[1]), "r"(a[2]), "r"(a[3]), "r"(b[0]), "r"(b[1]));
}

// k-interleave within each 8-group: fragment pairs (k, k+4) become adjacent
__device__ __forceinline__ int kperm(int k){
    return (k & ~7) | ((k & 3) << 1) | ((k >> 2) & 1);
}

// ---------------- 1) factorize params (k-permuted layout) ----------------
// log_q[i,j] = A_j + dot(X_i, W_j);  X=[s^2, s], W=[-0.5*iv, m*iv]
__global__ void prep_kernel(const float* __restrict__ f_mean,
                            const float* __restrict__ f_logvar,
                            const float* __restrict__ f_sample,
                            const float* __restrict__ z_mean,
                            const float* __restrict__ z_logvar,
                            const float* __restrict__ z_sample) {
    int j = blockIdx.x;
    int t = threadIdx.x;          // 256 threads
    __shared__ float sm[8];
    float part = 0.f;
    if (blockIdx.y == 0) {
        float lv = f_logvar[j*DF + t];
        float m  = f_mean  [j*DF + t];
        float s  = f_sample[j*DF + t];
        float iv = expf(-lv);
        int kp = kperm(t);
        g_Xf[j*KF + kp]      = s*s;
        g_Xf[j*KF + DF + kp] = s;
        g_Wf[j*KF + kp]      = -0.5f*iv;
        g_Wf[j*KF + DF + kp] = m*iv;
        part = lv + m*m*iv;
    } else {
        #pragma unroll
        for (int d = t; d < DZTOT; d += 256) {
            float lv = z_logvar[j*DZTOT + d];
            float m  = z_mean  [j*DZTOT + d];
            float s  = z_sample[j*DZTOT + d];
            float iv = expf(-lv);
            int kp = kperm(d);
            g_Xz[j*KZ + kp]         = s*s;
            g_Xz[j*KZ + DZTOT + kp] = s;
            g_Wz[j*KZ + kp]         = -0.5f*iv;
            g_Wz[j*KZ + DZTOT + kp] = m*iv;
            part += lv + m*m*iv;
        }
    }
    #pragma unroll
    for (int o = 16; o; o >>= 1) part += __shfl_xor_sync(0xffffffffu, part, o);
    if ((t & 31) == 0) sm[t >> 5] = part;
    __syncthreads();
    if (t == 0) {
        float r = ((sm[0]+sm[1])+(sm[2]+sm[3])) + ((sm[4]+sm[5])+(sm[6]+sm[7]));
        float D = (blockIdx.y == 0) ? (float)DF : (float)DZTOT;
        float A = -0.5f*(D*LOG_2PI + r);
        if (blockIdx.y == 0) g_Af[j] = A; else g_Az[j] = A;
    }
}

// ---------------- 2) mma.sync tf32 NT-GEMM with hi/lo compensation -------
// 384 identical CTAs of 128x64xK128. D += Ahi*Bhi + Ahi*Blo + Alo*Bhi.
__global__ void __launch_bounds__(256, 2) gemm_mma_kernel() {
    extern __shared__ float dsm[];

    int t    = threadIdx.x;
    int lane = t & 31;
    int wid  = t >> 5;
    int wm   = wid >> 1;          // 0..3 -> 32-row slab
    int wn   = wid & 1;           // 0..1 -> 32-col slab
    int g    = lane >> 2;         // groupID
    int c    = lane & 3;          // threadID_in_group

    // block mapping: [0,128) f split4 ; [128,384) z split8 — all uniform K128
    int b = blockIdx.x;
    const float* __restrict__ X;
    const float* __restrict__ W;
    float* __restrict__ P;
    int K, kOff, tile;
    if (b < SPLITF*32) {
        int s = b >> 5; tile = b & 31;
        X = g_Xf; W = g_Wf; P = g_Pf + s*(NB*NB); K = KF; kOff = s*KCH;
    } else {
        b -= SPLITF*32;
        int s = b >> 5; tile = b & 31;
        X = g_Xz; W = g_Wz; P = g_Pz + s*(NB*NB); K = KZ; kOff = s*KCH;
    }
    int rowBase = (tile >> 3) * BM;
    int colBase = (tile & 7) * BN;

    const float* Xb = X + rowBase*K + kOff;
    const float* Wb = W + colBase*K + kOff;

    float4 pre[3];
    auto ldg = [&](int kt){
        int kb = kt*BK;
        #pragma unroll
        for (int i = 0; i < 2; i++) {          // A: 128 rows x 4 float4
            int idx = t + 256*i, r = idx >> 2, c4 = idx & 3;
            pre[i] = *(const float4*)&Xb[r*K + kb + c4*4];
        }
        {                                      // B: 64 rows x 4 float4
            int r = t >> 2, c4 = t & 3;
            pre[2] = *(const float4*)&Wb[r*K + kb + c4*4];
        }
    };
    auto sts = [&](int s){
        char* st = (char*)dsm + s*ST_SIZE;
        #pragma unroll
        for (int i = 0; i < 2; i++) {
            int idx = t + 256*i, r = idx >> 2, c4 = idx & 3;
            float4 v = pre[i], h, l;
            h.x = tf32r(v.x); l.x = tf32r(v.x - h.x);
            h.y = tf32r(v.y); l.y = tf32r(v.y - h.y);
            h.z = tf32r(v.z); l.z = tf32r(v.z - h.z);
            h.w = tf32r(v.w); l.w = tf32r(v.w - h.w);
            int off = (r*ASTR + c4*4)*4;
            *(float4*)(st + off)           = h;
            *(float4*)(st + A_BYTES + off) = l;
        }
        {
            int r = t >> 2, c4 = t & 3;
            float4 v = pre[2], h, l;
            h.x = tf32r(v.x); l.x = tf32r(v.x - h.x);
            h.y = tf32r(v.y); l.y = tf32r(v.y - h.y);
            h.z = tf32r(v.z); l.z = tf32r(v.z - h.z);
            h.w = tf32r(v.w); l.w = tf32r(v.w - h.w);
            int off = (r*BSTR + c4*4)*4;
            *(float4*)(st + 2*A_BYTES + off)           = h;
            *(float4*)(st + 2*A_BYTES + B_BYTES + off) = l;
        }
    };

    float acc[2][4][4] = {};

    auto compute = [&](int s){
        const char* st = (const char*)dsm + s*ST_SIZE;
        const float* Ah = (const float*)st;
        const float* Al = (const float*)(st + A_BYTES);
        const float* Bh = (const float*)(st + 2*A_BYTES);
        const float* Bl = (const float*)(st + 2*A_BYTES + B_BYTES);
        #pragma unroll
        for (int g8 = 0; g8 < 2; g8++) {
            int ko = g8*8 + 2*c;
            uint32_t ah[2][4], al[2][4], bh[4][2], bl[4][2];
            #pragma unroll
            for (int ma = 0; ma < 2; ma++) {
                int r0 = (wm*32 + ma*16 + g)*ASTR + ko;
                float2 p0 = *(const float2*)&Ah[r0];
                float2 p1 = *(const float2*)&Ah[r0 + 8*ASTR];
                ah[ma][0] = __float_as_uint(p0.x); ah[ma][1] = __float_as_uint(p1.x);
                ah[ma][2] = __float_as_uint(p0.y); ah[ma][3] = __float_as_uint(p1.y);
                float2 q0 = *(const float2*)&Al[r0];
                float2 q1 = *(const float2*)&Al[r0 + 8*ASTR];
                al[ma][0] = __float_as_uint(q0.x); al[ma][1] = __float_as_uint(q1.x);
                al[ma][2] = __float_as_uint(q0.y); al[ma][3] = __float_as_uint(q1.y);
            }
            #pragma unroll
            for (int nb = 0; nb < 4; nb++) {
                int r0 = (wn*32 + nb*8 + g)*BSTR + ko;
                float2 p = *(const float2*)&Bh[r0];
                bh[nb][0] = __float_as_uint(p.x); bh[nb][1] = __float_as_uint(p.y);
                float2 q = *(const float2*)&Bl[r0];
                bl[nb][0] = __float_as_uint(q.x); bl[nb][1] = __float_as_uint(q.y);
            }
            #pragma unroll
            for (int ma = 0; ma < 2; ma++)
                #pragma unroll
                for (int nb = 0; nb < 4; nb++) {
                    mma8(acc[ma][nb], ah[ma], bh[nb]);
                    mma8(acc[ma][nb], ah[ma], bl[nb]);
                    mma8(acc[ma][nb], al[ma], bh[nb]);
                }
        }
    };

    ldg(0); sts(0); __syncthreads();
    for (int kt = 0; kt < NSTG; kt++) {
        int s = kt & 1;
        if (kt + 1 < NSTG) ldg(kt + 1);
        compute(s);
        if (kt + 1 < NSTG) { sts(s ^ 1); __syncthreads(); }
    }

    #pragma unroll
    for (int ma = 0; ma < 2; ma++) {
        int i0 = rowBase + wm*32 + ma*16 + g;
        #pragma unroll
        for (int nb = 0; nb < 4; nb++) {
            int j0 = colBase + wn*32 + nb*8 + 2*c;
            *(float2*)&P[ i0   *NB + j0] = make_float2(acc[ma][nb][0], acc[ma][nb][1]);
            *(float2*)&P[(i0+8)*NB + j0] = make_float2(acc[ma][nb][2], acc[ma][nb][3]);
        }
    }
}

// ---------------- 3) per-row LSE + fused final reduction -----------------
__device__ __forceinline__ float bred_max(float v, float* sm, int t) {
    #pragma unroll
    for (int o = 16; o; o >>= 1) v = fmaxf(v, __shfl_xor_sync(0xffffffffu, v, o));
    if ((t & 31) == 0) sm[t >> 5] = v;
    __syncthreads();
    v = fmaxf(fmaxf(sm[0], sm[1]), fmaxf(sm[2], sm[3]));
    __syncthreads();
    return v;
}
__device__ __forceinline__ float bred_sum(float v, float* sm, int t) {
    #pragma unroll
    for (int o = 16; o; o >>= 1) v += __shfl_xor_sync(0xffffffffu, v, o);
    if ((t & 31) == 0) sm[t >> 5] = v;
    __syncthreads();
    v = (sm[0] + sm[1]) + (sm[2] + sm[3]);
    __syncthreads();
    return v;
}

__global__ void lse_kernel(const int* __restrict__ num_train_p,
                           float* __restrict__ out, int out_size) {
    int i = blockIdx.x;
    int t = threadIdx.x;          // 128 threads, 4 cols each
    int j4 = t * 4;
    __shared__ float sm[4];
    __shared__ bool isLast;

    float a[4]  = {0.f, 0.f, 0.f, 0.f};
    float bb[4] = {0.f, 0.f, 0.f, 0.f};
    #pragma unroll
    for (int s = 0; s < SPLITF; s++) {
        float4 v = *(const float4*)&g_Pf[s*(NB*NB) + i*NB + j4];
        a[0] += v.x; a[1] += v.y; a[2] += v.z; a[3] += v.w;
    }
    #pragma unroll
    for (int s = 0; s < SPLITZ; s++) {
        float4 v = *(const float4*)&g_Pz[s*(NB*NB) + i*NB + j4];
        bb[0] += v.x; bb[1] += v.y; bb[2] += v.z; bb[3] += v.w;
    }
    float4 af = *(const float4*)&g_Af[j4];
    float4 az = *(const float4*)&g_Az[j4];
    a[0] += af.x; a[1] += af.y; a[2] += af.z; a[3] += af.w;
    bb[0] += az.x; bb[1] += az.y; bb[2] += az.z; bb[3] += az.w;
    float cc[4] = {a[0]+bb[0], a[1]+bb[1], a[2]+bb[2], a[3]+bb[3]};

    float Ma = bred_max(fmaxf(fmaxf(a[0], a[1]),   fmaxf(a[2], a[3])),   sm, t);
    float Mb = bred_max(fmaxf(fmaxf(bb[0], bb[1]), fmaxf(bb[2], bb[3])), sm, t);
    float Mc = bred_max(fmaxf(fmaxf(cc[0], cc[1]), fmaxf(cc[2], cc[3])), sm, t);

    float Sa = bred_sum((expf(a[0]-Ma)  + expf(a[1]-Ma))  + (expf(a[2]-Ma)  + expf(a[3]-Ma)),  sm, t);
    float Sb = bred_sum((expf(bb[0]-Mb) + expf(bb[1]-Mb)) + (expf(bb[2]-Mb) + expf(bb[3]-Mb)), sm, t);
    float Sc = bred_sum((expf(cc[0]-Mc) + expf(cc[1]-Mc)) + (expf(cc[2]-Mc) + expf(cc[3]-Mc)), sm, t);

    if (t == 0) {
        g_lse[0*NB + i] = Ma + logf(Sa);
        g_lse[1*NB + i] = Mb + logf(Sb);
        g_lse[2*NB + i] = Mc + logf(Sc);
        __threadfence();
        int v = atomicAdd(&g_ctr, 1);
        isLast = (v == NB - 1);
    }
    __syncthreads();

    if (isLast) {
        float s0 = 0.f, s1 = 0.f, s2 = 0.f;
        #pragma unroll
        for (int r = t; r < NB; r += 128) {
            s0 += g_lse[0*NB + r];
            s1 += g_lse[1*NB + r];
            s2 += g_lse[2*NB + r];
        }
        s0 = bred_sum(s0, sm, t);
        s1 = bred_sum(s1, sm, t);
        s2 = bred_sum(s2, sm, t);
        if (t == 0) {
            g_ctr = 0;
            int v = num_train_p[0];
            float nt;
            if (v > 0 && v < (1 << 30)) nt = (float)v;
            else nt = __int_as_float(v);
            float clogNM = logf(nt * (float)NB);
            float Hf  = -s0 / (float)NB + clogNM;
            float Hz  = -s1 / (float)NB + clogNM;
            float Hfz = -s2 / (float)NB + clogNM;
            float MI  = Hf + Hz - Hfz;
            if (out_size > 0) out[0] = MI;
            if (out_size > 1) out[1] = Hf;
            if (out_size > 2) out[2] = Hz;
            if (out_size > 3) out[3] = Hfz;
        }
    }
}

// ---------------- launch ----------------
extern "C" void kernel_launch(void* const* d_in, const int* in_sizes, int n_in,
                              void* d_out, int out_size) {
    const float* f_mean   = (const float*)d_in[0];
    const float* f_logvar = (const float*)d_in[1];
    const float* f_sample = (const float*)d_in[2];
    const float* z_mean   = (const float*)d_in[3];
    const float* z_logvar = (const float*)d_in[4];
    const float* z_sample = (const float*)d_in[5];
    const int*   num_train = (const int*)d_in[6];

    cudaFuncSetAttribute(gemm_mma_kernel,
                         cudaFuncAttributeMaxDynamicSharedMemorySize, SMEM_DYN);

    prep_kernel<<<dim3(NB, 2), 256>>>(f_mean, f_logvar, f_sample,
                                      z_mean, z_logvar, z_sample);
    gemm_mma_kernel<<<(SPLITF + SPLITZ) * 32, 256, SMEM_DYN>>>();
    lse_kernel<<<NB, 128>>>(num_train, (float*)d_out, out_size);
}

// round 14
// speedup vs baseline: 4.0829x; 1.4885x over previous
#include <cuda_runtime.h>
#include <cuda_fp16.h>
#include <math.h>
#include <stdint.h>

#define NB    512
#define DF    256
#define DZTOT 512
#define KF    512            // 2*DF   halfs (concat [s^2, s], pair-permuted)
#define KZ    1024           // 2*DZTOT
#define BM    128
#define BN    64
#define BK    32             // halfs per stage
#define NSTG  4              // KCH 128 / BK 32
#define KCH   128
#define SPLITF 4
#define SPLITZ 8
#define LOG_2PI 1.8378770664093453f

// smem (uint32 units): Ahi[128][24], Alo, Bhi[64][24], Blo ; data = 16 u32/row
#define ASTRU 24
#define U_AHI 0
#define U_ALO 3072           // 128*24
#define U_BHI 6144
#define U_BLO 7680           // +64*24
#define U_STAGE 9216
#define SMEM_DYN (2*U_STAGE*4)   // 73728 B -> 3 CTAs/SM

// ---------------- scratch ----------------
__device__ uint32_t g_Xfh[NB*KF/2];
__device__ uint32_t g_Xfl[NB*KF/2];
__device__ uint32_t g_Wfh[NB*KF/2];
__device__ uint32_t g_Wfl[NB*KF/2];
__device__ uint32_t g_Xzh[NB*KZ/2];
__device__ uint32_t g_Xzl[NB*KZ/2];
__device__ uint32_t g_Wzh[NB*KZ/2];
__device__ uint32_t g_Wzl[NB*KZ/2];
__device__ float g_Af[NB];
__device__ float g_Az[NB];
__device__ float g_Pf[SPLITF*NB*NB];
__device__ float g_Pz[SPLITZ*NB*NB];
__device__ float g_lse[3*NB];
__device__ int   g_ctr;

__device__ __forceinline__ uint32_t smem_u32(const void* p){
    uint32_t a; asm("{ .reg .u64 t; cvta.to.shared.u64 t, %1; cvt.u32.u64 %0, t; }" : "=r"(a) : "l"(p)); return a;
}
__device__ __forceinline__ void cp16(uint32_t dst, const void* src){
    asm volatile("cp.async.cg.shared.global [%0], [%1], 16;" :: "r"(dst), "l"(src));
}
__device__ __forceinline__ void mma16(float* d, uint32_t a0, uint32_t a1, uint32_t a2, uint32_t a3,
                                      uint32_t b0, uint32_t b1){
    asm("mma.sync.aligned.m16n8k16.row.col.f32.f16.f16.f32 "
        "{%0,%1,%2,%3}, {%4,%5,%6,%7}, {%8,%9}, {%0,%1,%2,%3};"
        : "+f"(d[0]), "+f"(d[1]), "+f"(d[2]), "+f"(d[3])
        : "r"(a0), "r"(a1), "r"(a2), "r"(a3), "r"(b0), "r"(b1));
}

// pair-permute k so fragment pairs (pair c, pair c+4) are adjacent uint32s
__device__ __forceinline__ int kmap(int k){
    int p = k >> 1, q = k & 1;
    int pp = (p & ~7) | ((p & 3) << 1) | ((p >> 2) & 1);
    return pp*2 + q;
}

__device__ __forceinline__ void hsplit(float x, __half& h, __half& l){
    h = __float2half_rn(x);
    l = __float2half_rn(x - __half2float(h));
}

// ---------------- 1) factorize + fp16 hi/lo split ----------------
// log_q[i,j] = A_j + dot(X_i, W_j);  X=[s^2, s], W=[-0.5*iv, m*iv]
__global__ void prep_kernel(const float* __restrict__ f_mean,
                            const float* __restrict__ f_logvar,
                            const float* __restrict__ f_sample,
                            const float* __restrict__ z_mean,
                            const float* __restrict__ z_logvar,
                            const float* __restrict__ z_sample) {
    int j = blockIdx.x;
    int t = threadIdx.x;          // 256 threads
    __shared__ float sm[8];
    float part = 0.f;

    if (blockIdx.y == 0) {
        __half* Xh = (__half*)g_Xfh; __half* Xl = (__half*)g_Xfl;
        __half* Wh = (__half*)g_Wfh; __half* Wl = (__half*)g_Wfl;
        float lv = f_logvar[j*DF + t];
        float m  = f_mean  [j*DF + t];
        float s  = f_sample[j*DF + t];
        float iv = expf(-lv);
        int k0 = kmap(t), k1 = kmap(DF + t);
        __half h, l;
        hsplit(s*s,      h, l); Xh[j*KF + k0] = h; Xl[j*KF + k0] = l;
        hsplit(s,        h, l); Xh[j*KF + k1] = h; Xl[j*KF + k1] = l;
        hsplit(-0.5f*iv, h, l); Wh[j*KF + k0] = h; Wl[j*KF + k0] = l;
        hsplit(m*iv,     h, l); Wh[j*KF + k1] = h; Wl[j*KF + k1] = l;
        part = lv + m*m*iv;
    } else {
        __half* Xh = (__half*)g_Xzh; __half* Xl = (__half*)g_Xzl;
        __half* Wh = (__half*)g_Wzh; __half* Wl = (__half*)g_Wzl;
        #pragma unroll
        for (int d = t; d < DZTOT; d += 256) {
            float lv = z_logvar[j*DZTOT + d];
            float m  = z_mean  [j*DZTOT + d];
            float s  = z_sample[j*DZTOT + d];
            float iv = expf(-lv);
            int k0 = kmap(d), k1 = kmap(DZTOT + d);
            __half h, l;
            hsplit(s*s,      h, l); Xh[j*KZ + k0] = h; Xl[j*KZ + k0] = l;
            hsplit(s,        h, l); Xh[j*KZ + k1] = h; Xl[j*KZ + k1] = l;
            hsplit(-0.5f*iv, h, l); Wh[j*KZ + k0] = h; Wl[j*KZ + k0] = l;
            hsplit(m*iv,     h, l); Wh[j*KZ + k1] = h; Wl[j*KZ + k1] = l;
            part += lv + m*m*iv;
        }
    }
    #pragma unroll
    for (int o = 16; o; o >>= 1) part += __shfl_xor_sync(0xffffffffu, part, o);
    if ((t & 31) == 0) sm[t >> 5] = part;
    __syncthreads();
    if (t == 0) {
        float r = ((sm[0]+sm[1])+(sm[2]+sm[3])) + ((sm[4]+sm[5])+(sm[6]+sm[7]));
        float D = (blockIdx.y == 0) ? (float)DF : (float)DZTOT;
        float A = -0.5f*(D*LOG_2PI + r);
        if (blockIdx.y == 0) g_Af[j] = A; else g_Az[j] = A;
    }
}

// ---------------- 2) fp16 hi/lo mma.sync NT-GEMM -------------------------
// 384 identical CTAs of 128x64xK128. D += Ah*Bh + Al*Bh + Ah*Bl (fp32 acc).
__global__ void __launch_bounds__(256, 3) gemm_mma_kernel() {
    extern __shared__ uint32_t dsm[];
    uint32_t sbase = smem_u32(dsm);

    int t    = threadIdx.x;
    int lane = t & 31;
    int wid  = t >> 5;
    int wm   = wid >> 1;          // 0..3 -> 32-row slab
    int wn   = wid & 1;           // 0..1 -> 32-col slab
    int g    = lane >> 2;
    int c    = lane & 3;

    // block mapping: [0,128) f split4 ; [128,384) z split8 — uniform K128
    int b = blockIdx.x;
    const uint32_t* __restrict__ Xh;
    const uint32_t* __restrict__ Xl;
    const uint32_t* __restrict__ Wh;
    const uint32_t* __restrict__ Wl;
    float* __restrict__ P;
    int Ku, kOffU, tile;
    if (b < SPLITF*32) {
        int s = b >> 5; tile = b & 31;
        Xh = g_Xfh; Xl = g_Xfl; Wh = g_Wfh; Wl = g_Wfl;
        P = g_Pf + s*(NB*NB); Ku = KF/2; kOffU = s*(KCH/2);
    } else {
        b -= SPLITF*32;
        int s = b >> 5; tile = b & 31;
        Xh = g_Xzh; Xl = g_Xzl; Wh = g_Wzh; Wl = g_Wzl;
        P = g_Pz + s*(NB*NB); Ku = KZ/2; kOffU = s*(KCH/2);
    }
    int rowBase = (tile >> 3) * BM;
    int colBase = (tile & 7) * BN;

    const uint32_t* Xhb = Xh + rowBase*Ku + kOffU;
    const uint32_t* Xlb = Xl + rowBase*Ku + kOffU;
    const uint32_t* Whb = Wh + colBase*Ku + kOffU;
    const uint32_t* Wlb = Wl + colBase*Ku + kOffU;

    auto issue = [&](int kt, int s){
        uint32_t sb = sbase + s*(U_STAGE*4);
        int kb = kt*16;                          // u32 offset in row
        #pragma unroll
        for (int i = 0; i < 2; i++) {            // A: 512 chunks of 16B
            int id = t + 256*i, r = id >> 2, cc = id & 3;
            cp16(sb + (U_AHI + r*ASTRU + cc*4)*4, Xhb + r*Ku + kb + cc*4);
            cp16(sb + (U_ALO + r*ASTRU + cc*4)*4, Xlb + r*Ku + kb + cc*4);
        }
        {                                        // B: 256 chunks
            int r = t >> 2, cc = t & 3;
            cp16(sb + (U_BHI + r*ASTRU + cc*4)*4, Whb + r*Ku + kb + cc*4);
            cp16(sb + (U_BLO + r*ASTRU + cc*4)*4, Wlb + r*Ku + kb + cc*4);
        }
        asm volatile("cp.async.commit_group;" ::: "memory");
    };

    float acc[2][4][4] = {};

    auto compute = [&](int s){
        const uint32_t* st = dsm + s*U_STAGE;
        #pragma unroll
        for (int g8 = 0; g8 < 2; g8++) {
            int ko = g8*8 + 2*c;
            uint2 AH[2][2], BH[4], AX[2][2];
            #pragma unroll
            for (int ma = 0; ma < 2; ma++) {
                int r0 = (wm*32 + ma*16 + g)*ASTRU + ko;
                AH[ma][0] = *(const uint2*)&st[U_AHI + r0];
                AH[ma][1] = *(const uint2*)&st[U_AHI + r0 + 8*ASTRU];
            }
            #pragma unroll
            for (int nb = 0; nb < 4; nb++)
                BH[nb] = *(const uint2*)&st[U_BHI + (wn*32 + nb*8 + g)*ASTRU + ko];
            #pragma unroll
            for (int ma = 0; ma < 2; ma++)
                #pragma unroll
                for (int nb = 0; nb < 4; nb++)
                    mma16(acc[ma][nb], AH[ma][0].x, AH[ma][1].x, AH[ma][0].y, AH[ma][1].y,
                          BH[nb].x, BH[nb].y);
            // A-lo pass
            #pragma unroll
            for (int ma = 0; ma < 2; ma++) {
                int r0 = (wm*32 + ma*16 + g)*ASTRU + ko;
                AX[ma][0] = *(const uint2*)&st[U_ALO + r0];
                AX[ma][1] = *(const uint2*)&st[U_ALO + r0 + 8*ASTRU];
            }
            #pragma unroll
            for (int ma = 0; ma < 2; ma++)
                #pragma unroll
                for (int nb = 0; nb < 4; nb++)
                    mma16(acc[ma][nb], AX[ma][0].x, AX[ma][1].x, AX[ma][0].y, AX[ma][1].y,
                          BH[nb].x, BH[nb].y);
            // B-lo pass (reuse BH regs)
            #pragma unroll
            for (int nb = 0; nb < 4; nb++)
                BH[nb] = *(const uint2*)&st[U_BLO + (wn*32 + nb*8 + g)*ASTRU + ko];
            #pragma unroll
            for (int ma = 0; ma < 2; ma++)
                #pragma unroll
                for (int nb = 0; nb < 4; nb++)
                    mma16(acc[ma][nb], AH[ma][0].x, AH[ma][1].x, AH[ma][0].y, AH[ma][1].y,
                          BH[nb].x, BH[nb].y);
        }
    };

    issue(0, 0);
    for (int kt = 0; kt < NSTG; kt++) {
        int s = kt & 1;
        if (kt + 1 < NSTG) {
            issue(kt + 1, s ^ 1);
            asm volatile("cp.async.wait_group 1;" ::: "memory");
        } else {
            asm volatile("cp.async.wait_group 0;" ::: "memory");
        }
        __syncthreads();
        compute(s);
        __syncthreads();
    }

    #pragma unroll
    for (int ma = 0; ma < 2; ma++) {
        int i0 = rowBase + wm*32 + ma*16 + g;
        #pragma unroll
        for (int nb = 0; nb < 4; nb++) {
            int j0 = colBase + wn*32 + nb*8 + 2*c;
            *(float2*)&P[ i0   *NB + j0] = make_float2(acc[ma][nb][0], acc[ma][nb][1]);
            *(float2*)&P[(i0+8)*NB + j0] = make_float2(acc[ma][nb][2], acc[ma][nb][3]);
        }
    }
}

// ---------------- 3) per-row LSE + fused final reduction -----------------
__device__ __forceinline__ float bred_max(float v, float* sm, int t) {
    #pragma unroll
    for (int o = 16; o; o >>= 1) v = fmaxf(v, __shfl_xor_sync(0xffffffffu, v, o));
    if ((t & 31) == 0) sm[t >> 5] = v;
    __syncthreads();
    v = fmaxf(fmaxf(sm[0], sm[1]), fmaxf(sm[2], sm[3]));
    __syncthreads();
    return v;
}
__device__ __forceinline__ float bred_sum(float v, float* sm, int t) {
    #pragma unroll
    for (int o = 16; o; o >>= 1) v += __shfl_xor_sync(0xffffffffu, v, o);
    if ((t & 31) == 0) sm[t >> 5] = v;
    __syncthreads();
    v = (sm[0] + sm[1]) + (sm[2] + sm[3]);
    __syncthreads();
    return v;
}

__global__ void lse_kernel(const int* __restrict__ num_train_p,
                           float* __restrict__ out, int out_size) {
    int i = blockIdx.x;
    int t = threadIdx.x;          // 128 threads, 4 cols each
    int j4 = t * 4;
    __shared__ float sm[4];
    __shared__ bool isLast;

    float a[4]  = {0.f, 0.f, 0.f, 0.f};
    float bb[4] = {0.f, 0.f, 0.f, 0.f};
    #pragma unroll
    for (int s = 0; s < SPLITF; s++) {
        float4 v = *(const float4*)&g_Pf[s*(NB*NB) + i*NB + j4];
        a[0] += v.x; a[1] += v.y; a[2] += v.z; a[3] += v.w;
    }
    #pragma unroll
    for (int s = 0; s < SPLITZ; s++) {
        float4 v = *(const float4*)&g_Pz[s*(NB*NB) + i*NB + j4];
        bb[0] += v.x; bb[1] += v.y; bb[2] += v.z; bb[3] += v.w;
    }
    float4 af = *(const float4*)&g_Af[j4];
    float4 az = *(const float4*)&g_Az[j4];
    a[0] += af.x; a[1] += af.y; a[2] += af.z; a[3] += af.w;
    bb[0] += az.x; bb[1] += az.y; bb[2] += az.z; bb[3] += az.w;
    float cc[4] = {a[0]+bb[0], a[1]+bb[1], a[2]+bb[2], a[3]+bb[3]};

    float Ma = bred_max(fmaxf(fmaxf(a[0], a[1]),   fmaxf(a[2], a[3])),   sm, t);
    float Mb = bred_max(fmaxf(fmaxf(bb[0], bb[1]), fmaxf(bb[2], bb[3])), sm, t);
    float Mc = bred_max(fmaxf(fmaxf(cc[0], cc[1]), fmaxf(cc[2], cc[3])), sm, t);

    float Sa = bred_sum((expf(a[0]-Ma)  + expf(a[1]-Ma))  + (expf(a[2]-Ma)  + expf(a[3]-Ma)),  sm, t);
    float Sb = bred_sum((expf(bb[0]-Mb) + expf(bb[1]-Mb)) + (expf(bb[2]-Mb) + expf(bb[3]-Mb)), sm, t);
    float Sc = bred_sum((expf(cc[0]-Mc) + expf(cc[1]-Mc)) + (expf(cc[2]-Mc) + expf(cc[3]-Mc)), sm, t);

    if (t == 0) {
        g_lse[0*NB + i] = Ma + logf(Sa);
        g_lse[1*NB + i] = Mb + logf(Sb);
        g_lse[2*NB + i] = Mc + logf(Sc);
        __threadfence();
        int v = atomicAdd(&g_ctr, 1);
        isLast = (v == NB - 1);
    }
    __syncthreads();

    if (isLast) {
        float s0 = 0.f, s1 = 0.f, s2 = 0.f;
        #pragma unroll
        for (int r = t; r < NB; r += 128) {
            s0 += g_lse[0*NB + r];
            s1 += g_lse[1*NB + r];
            s2 += g_lse[2*NB + r];
        }
        s0 = bred_sum(s0, sm, t);
        s1 = bred_sum(s1, sm, t);
        s2 = bred_sum(s2, sm, t);
        if (t == 0) {
            g_ctr = 0;
            int v = num_train_p[0];
            float nt;
            if (v > 0 && v < (1 << 30)) nt = (float)v;
            else nt = __int_as_float(v);
            float clogNM = logf(nt * (float)NB);
            float Hf  = -s0 / (float)NB + clogNM;
            float Hz  = -s1 / (float)NB + clogNM;
            float Hfz = -s2 / (float)NB + clogNM;
            float MI  = Hf + Hz - Hfz;
            if (out_size > 0) out[0] = MI;
            if (out_size > 1) out[1] = Hf;
            if (out_size > 2) out[2] = Hz;
            if (out_size > 3) out[3] = Hfz;
        }
    }
}

// ---------------- launch ----------------
extern "C" void kernel_launch(void* const* d_in, const int* in_sizes, int n_in,
                              void* d_out, int out_size) {
    const float* f_mean   = (const float*)d_in[0];
    const float* f_logvar = (const float*)d_in[1];
    const float* f_sample = (const float*)d_in[2];
    const float* z_mean   = (const float*)d_in[3];
    const float* z_logvar = (const float*)d_in[4];
    const float* z_sample = (const float*)d_in[5];
    const int*   num_train = (const int*)d_in[6];

    cudaFuncSetAttribute(gemm_mma_kernel,
                         cudaFuncAttributeMaxDynamicSharedMemorySize, SMEM_DYN);

    prep_kernel<<<dim3(NB, 2), 256>>>(f_mean, f_logvar, f_sample,
                                      z_mean, z_logvar, z_sample);
    gemm_mma_kernel<<<(SPLITF + SPLITZ) * 32, 256, SMEM_DYN>>>();
    lse_kernel<<<NB, 128>>>(num_train, (float*)d_out, out_size);
}

// round 15
// speedup vs baseline: 4.1518x; 1.0169x over previous
#include <cuda_runtime.h>
#include <cuda_fp16.h>
#include <math.h>
#include <stdint.h>

#define NB    512
#define DF    256
#define DZTOT 512
#define KF    512            // 2*DF   halfs (concat [s^2, s], pair-permuted)
#define KZ    1024           // 2*DZTOT
#define BM    128
#define BN    64
#define BK    32             // halfs per stage
#define NSTG  4              // KCH 128 / BK 32
#define KCH   128
#define SPLITF 4
#define SPLITZ 8
#define LOG_2PI 1.8378770664093453f

// smem (uint32 units): Ahi[128][24], Alo, Bhi[64][24], Blo ; data = 16 u32/row
#define ASTRU 24
#define U_AHI 0
#define U_ALO 3072           // 128*24
#define U_BHI 6144
#define U_BLO 7680           // +64*24
#define U_STAGE 9216
#define SMEM_DYN (2*U_STAGE*4)   // 73728 B -> 3 CTAs/SM

// ---------------- scratch ----------------
__device__ uint32_t g_Xfh[NB*KF/2];
__device__ uint32_t g_Xfl[NB*KF/2];
__device__ uint32_t g_Wfh[NB*KF/2];
__device__ uint32_t g_Wfl[NB*KF/2];
__device__ uint32_t g_Xzh[NB*KZ/2];
__device__ uint32_t g_Xzl[NB*KZ/2];
__device__ uint32_t g_Wzh[NB*KZ/2];
__device__ uint32_t g_Wzl[NB*KZ/2];
__device__ float g_Af[NB];
__device__ float g_Az[NB];
__device__ float g_Pf[SPLITF*NB*NB];
__device__ float g_Pz[SPLITZ*NB*NB];
__device__ float g_lse[3*NB];
__device__ int   g_ctr;

__device__ __forceinline__ uint32_t smem_u32(const void* p){
    uint32_t a; asm("{ .reg .u64 t; cvta.to.shared.u64 t, %1; cvt.u32.u64 %0, t; }" : "=r"(a) : "l"(p)); return a;
}
__device__ __forceinline__ void cp16(uint32_t dst, const void* src){
    asm volatile("cp.async.cg.shared.global [%0], [%1], 16;" :: "r"(dst), "l"(src));
}
__device__ __forceinline__ void mma16(float* d, uint32_t a0, uint32_t a1, uint32_t a2, uint32_t a3,
                                      uint32_t b0, uint32_t b1){
    asm("mma.sync.aligned.m16n8k16.row.col.f32.f16.f16.f32 "
        "{%0,%1,%2,%3}, {%4,%5,%6,%7}, {%8,%9}, {%0,%1,%2,%3};"
        : "+f"(d[0]), "+f"(d[1]), "+f"(d[2]), "+f"(d[3])
        : "r"(a0), "r"(a1), "r"(a2), "r"(a3), "r"(b0), "r"(b1));
}

// pair-level permutation: fragment pairs (pair c, pair c+4) become adjacent u32s
__device__ __forceinline__ int pmap(int p){
    return (p & ~7) | ((p & 3) << 1) | ((p >> 2) & 1);
}

// pack two fp32 values into hi/lo __half2 words
__device__ __forceinline__ void hsplit2(float x0, float x1, uint32_t& hu, uint32_t& lu){
    __half h0 = __float2half_rn(x0);
    __half h1 = __float2half_rn(x1);
    __half l0 = __float2half_rn(x0 - __half2float(h0));
    __half l1 = __float2half_rn(x1 - __half2float(h1));
    __half2 hh = __halves2half2(h0, h1);
    __half2 ll = __halves2half2(l0, l1);
    hu = *reinterpret_cast<uint32_t*>(&hh);
    lu = *reinterpret_cast<uint32_t*>(&ll);
}

// ---------------- 1) factorize + fp16 hi/lo split (pair-granular) --------
// log_q[i,j] = A_j + dot(X_i, W_j);  X=[s^2, s], W=[-0.5*iv, m*iv]
__global__ void prep_kernel(const float* __restrict__ f_mean,
                            const float* __restrict__ f_logvar,
                            const float* __restrict__ f_sample,
                            const float* __restrict__ z_mean,
                            const float* __restrict__ z_logvar,
                            const float* __restrict__ z_sample) {
    int j = blockIdx.x;
    int t = threadIdx.x;          // 128 threads, one k-pair per region
    __shared__ float sm[4];
    float part = 0.f;

    if (blockIdx.y == 0) {
        float2 lv = *(const float2*)&f_logvar[j*DF + 2*t];
        float2 m  = *(const float2*)&f_mean  [j*DF + 2*t];
        float2 s  = *(const float2*)&f_sample[j*DF + 2*t];
        float iv0 = expf(-lv.x), iv1 = expf(-lv.y);
        int p0 = pmap(t);          // s^2 / -iv/2 region
        int p1 = pmap(128 + t);    // s / m*iv region
        uint32_t hu, lu;
        hsplit2(s.x*s.x,    s.y*s.y,    hu, lu); g_Xfh[j*256 + p0] = hu; g_Xfl[j*256 + p0] = lu;
        hsplit2(s.x,        s.y,        hu, lu); g_Xfh[j*256 + p1] = hu; g_Xfl[j*256 + p1] = lu;
        hsplit2(-0.5f*iv0,  -0.5f*iv1,  hu, lu); g_Wfh[j*256 + p0] = hu; g_Wfl[j*256 + p0] = lu;
        hsplit2(m.x*iv0,    m.y*iv1,    hu, lu); g_Wfh[j*256 + p1] = hu; g_Wfl[j*256 + p1] = lu;
        part = (lv.x + m.x*m.x*iv0) + (lv.y + m.y*m.y*iv1);
    } else {
        #pragma unroll
        for (int it = 0; it < 2; it++) {
            int pd = t + 128*it;              // pair index within d-region (0..255)
            float2 lv = *(const float2*)&z_logvar[j*DZTOT + 2*pd];
            float2 m  = *(const float2*)&z_mean  [j*DZTOT + 2*pd];
            float2 s  = *(const float2*)&z_sample[j*DZTOT + 2*pd];
            float iv0 = expf(-lv.x), iv1 = expf(-lv.y);
            int p0 = pmap(pd);
            int p1 = pmap(256 + pd);
            uint32_t hu, lu;
            hsplit2(s.x*s.x,   s.y*s.y,   hu, lu); g_Xzh[j*512 + p0] = hu; g_Xzl[j*512 + p0] = lu;
            hsplit2(s.x,       s.y,       hu, lu); g_Xzh[j*512 + p1] = hu; g_Xzl[j*512 + p1] = lu;
            hsplit2(-0.5f*iv0, -0.5f*iv1, hu, lu); g_Wzh[j*512 + p0] = hu; g_Wzl[j*512 + p0] = lu;
            hsplit2(m.x*iv0,   m.y*iv1,   hu, lu); g_Wzh[j*512 + p1] = hu; g_Wzl[j*512 + p1] = lu;
            part += (lv.x + m.x*m.x*iv0) + (lv.y + m.y*m.y*iv1);
        }
    }
    #pragma unroll
    for (int o = 16; o; o >>= 1) part += __shfl_xor_sync(0xffffffffu, part, o);
    if ((t & 31) == 0) sm[t >> 5] = part;
    __syncthreads();
    if (t == 0) {
        float r = (sm[0] + sm[1]) + (sm[2] + sm[3]);
        float D = (blockIdx.y == 0) ? (float)DF : (float)DZTOT;
        float A = -0.5f*(D*LOG_2PI + r);
        if (blockIdx.y == 0) g_Af[j] = A; else g_Az[j] = A;
    }
}

// ---------------- 2) fp16 hi/lo mma.sync NT-GEMM -------------------------
// 384 identical CTAs of 128x64xK128. D += Ah*Bh + Al*Bh + Ah*Bl (fp32 acc).
__global__ void __launch_bounds__(256, 3) gemm_mma_kernel() {
    extern __shared__ uint32_t dsm[];
    uint32_t sbase = smem_u32(dsm);

    int t    = threadIdx.x;
    int lane = t & 31;
    int wid  = t >> 5;
    int wm   = wid >> 1;          // 0..3 -> 32-row slab
    int wn   = wid & 1;           // 0..1 -> 32-col slab
    int g    = lane >> 2;
    int c    = lane & 3;

    // block mapping: [0,128) f split4 ; [128,384) z split8 — uniform K128
    int b = blockIdx.x;
    const uint32_t* __restrict__ Xh;
    const uint32_t* __restrict__ Xl;
    const uint32_t* __restrict__ Wh;
    const uint32_t* __restrict__ Wl;
    float* __restrict__ P;
    int Ku, kOffU, tile;
    if (b < SPLITF*32) {
        int s = b >> 5; tile = b & 31;
        Xh = g_Xfh; Xl = g_Xfl; Wh = g_Wfh; Wl = g_Wfl;
        P = g_Pf + s*(NB*NB); Ku = KF/2; kOffU = s*(KCH/2);
    } else {
        b -= SPLITF*32;
        int s = b >> 5; tile = b & 31;
        Xh = g_Xzh; Xl = g_Xzl; Wh = g_Wzh; Wl = g_Wzl;
        P = g_Pz + s*(NB*NB); Ku = KZ/2; kOffU = s*(KCH/2);
    }
    int rowBase = (tile >> 3) * BM;
    int colBase = (tile & 7) * BN;

    const uint32_t* Xhb = Xh + rowBase*Ku + kOffU;
    const uint32_t* Xlb = Xl + rowBase*Ku + kOffU;
    const uint32_t* Whb = Wh + colBase*Ku + kOffU;
    const uint32_t* Wlb = Wl + colBase*Ku + kOffU;

    auto issue = [&](int kt, int s){
        uint32_t sb = sbase + s*(U_STAGE*4);
        int kb = kt*16;                          // u32 offset in row
        #pragma unroll
        for (int i = 0; i < 2; i++) {            // A: 512 chunks of 16B
            int id = t + 256*i, r = id >> 2, cc = id & 3;
            cp16(sb + (U_AHI + r*ASTRU + cc*4)*4, Xhb + r*Ku + kb + cc*4);
            cp16(sb + (U_ALO + r*ASTRU + cc*4)*4, Xlb + r*Ku + kb + cc*4);
        }
        {                                        // B: 256 chunks
            int r = t >> 2, cc = t & 3;
            cp16(sb + (U_BHI + r*ASTRU + cc*4)*4, Whb + r*Ku + kb + cc*4);
            cp16(sb + (U_BLO + r*ASTRU + cc*4)*4, Wlb + r*Ku + kb + cc*4);
        }
        asm volatile("cp.async.commit_group;" ::: "memory");
    };

    float acc[2][4][4] = {};

    auto compute = [&](int s){
        const uint32_t* st = dsm + s*U_STAGE;
        #pragma unroll
        for (int g8 = 0; g8 < 2; g8++) {
            int ko = g8*8 + 2*c;
            uint2 AH[2][2], BH[4], AX[2][2];
            #pragma unroll
            for (int ma = 0; ma < 2; ma++) {
                int r0 = (wm*32 + ma*16 + g)*ASTRU + ko;
                AH[ma][0] = *(const uint2*)&st[U_AHI + r0];
                AH[ma][1] = *(const uint2*)&st[U_AHI + r0 + 8*ASTRU];
            }
            #pragma unroll
            for (int nb = 0; nb < 4; nb++)
                BH[nb] = *(const uint2*)&st[U_BHI + (wn*32 + nb*8 + g)*ASTRU + ko];
            #pragma unroll
            for (int ma = 0; ma < 2; ma++)
                #pragma unroll
                for (int nb = 0; nb < 4; nb++)
                    mma16(acc[ma][nb], AH[ma][0].x, AH[ma][1].x, AH[ma][0].y, AH[ma][1].y,
                          BH[nb].x, BH[nb].y);
            // A-lo pass
            #pragma unroll
            for (int ma = 0; ma < 2; ma++) {
                int r0 = (wm*32 + ma*16 + g)*ASTRU + ko;
                AX[ma][0] = *(const uint2*)&st[U_ALO + r0];
                AX[ma][1] = *(const uint2*)&st[U_ALO + r0 + 8*ASTRU];
            }
            #pragma unroll
            for (int ma = 0; ma < 2; ma++)
                #pragma unroll
                for (int nb = 0; nb < 4; nb++)
                    mma16(acc[ma][nb], AX[ma][0].x, AX[ma][1].x, AX[ma][0].y, AX[ma][1].y,
                          BH[nb].x, BH[nb].y);
            // B-lo pass (reuse BH regs)
            #pragma unroll
            for (int nb = 0; nb < 4; nb++)
                BH[nb] = *(const uint2*)&st[U_BLO + (wn*32 + nb*8 + g)*ASTRU + ko];
            #pragma unroll
            for (int ma = 0; ma < 2; ma++)
                #pragma unroll
                for (int nb = 0; nb < 4; nb++)
                    mma16(acc[ma][nb], AH[ma][0].x, AH[ma][1].x, AH[ma][0].y, AH[ma][1].y,
                          BH[nb].x, BH[nb].y);
        }
    };

    issue(0, 0);
    for (int kt = 0; kt < NSTG; kt++) {
        int s = kt & 1;
        if (kt + 1 < NSTG) {
            issue(kt + 1, s ^ 1);
            asm volatile("cp.async.wait_group 1;" ::: "memory");
        } else {
            asm volatile("cp.async.wait_group 0;" ::: "memory");
        }
        __syncthreads();
        compute(s);
        __syncthreads();
    }

    #pragma unroll
    for (int ma = 0; ma < 2; ma++) {
        int i0 = rowBase + wm*32 + ma*16 + g;
        #pragma unroll
        for (int nb = 0; nb < 4; nb++) {
            int j0 = colBase + wn*32 + nb*8 + 2*c;
            *(float2*)&P[ i0   *NB + j0] = make_float2(acc[ma][nb][0], acc[ma][nb][1]);
            *(float2*)&P[(i0+8)*NB + j0] = make_float2(acc[ma][nb][2], acc[ma][nb][3]);
        }
    }
}

// ---------------- 3) per-row LSE + fused final reduction -----------------
__device__ __forceinline__ float bred_max(float v, float* sm, int t) {
    #pragma unroll
    for (int o = 16; o; o >>= 1) v = fmaxf(v, __shfl_xor_sync(0xffffffffu, v, o));
    if ((t & 31) == 0) sm[t >> 5] = v;
    __syncthreads();
    v = fmaxf(fmaxf(sm[0], sm[1]), fmaxf(sm[2], sm[3]));
    __syncthreads();
    return v;
}
__device__ __forceinline__ float bred_sum(float v, float* sm, int t) {
    #pragma unroll
    for (int o = 16; o; o >>= 1) v += __shfl_xor_sync(0xffffffffu, v, o);
    if ((t & 31) == 0) sm[t >> 5] = v;
    __syncthreads();
    v = (sm[0] + sm[1]) + (sm[2] + sm[3]);
    __syncthreads();
    return v;
}

__global__ void lse_kernel(const int* __restrict__ num_train_p,
                           float* __restrict__ out, int out_size) {
    int i = blockIdx.x;
    int t = threadIdx.x;          // 128 threads, 4 cols each
    int j4 = t * 4;
    __shared__ float sm[4];
    __shared__ bool isLast;

    float a[4]  = {0.f, 0.f, 0.f, 0.f};
    float bb[4] = {0.f, 0.f, 0.f, 0.f};
    #pragma unroll
    for (int s = 0; s < SPLITF; s++) {
        float4 v = *(const float4*)&g_Pf[s*(NB*NB) + i*NB + j4];
        a[0] += v.x; a[1] += v.y; a[2] += v.z; a[3] += v.w;
    }
    #pragma unroll
    for (int s = 0; s < SPLITZ; s++) {
        float4 v = *(const float4*)&g_Pz[s*(NB*NB) + i*NB + j4];
        bb[0] += v.x; bb[1] += v.y; bb[2] += v.z; bb[3] += v.w;
    }
    float4 af = *(const float4*)&g_Af[j4];
    float4 az = *(const float4*)&g_Az[j4];
    a[0] += af.x; a[1] += af.y; a[2] += af.z; a[3] += af.w;
    bb[0] += az.x; bb[1] += az.y; bb[2] += az.z; bb[3] += az.w;
    float cc[4] = {a[0]+bb[0], a[1]+bb[1], a[2]+bb[2], a[3]+bb[3]};

    float Ma = bred_max(fmaxf(fmaxf(a[0], a[1]),   fmaxf(a[2], a[3])),   sm, t);
    float Mb = bred_max(fmaxf(fmaxf(bb[0], bb[1]), fmaxf(bb[2], bb[3])), sm, t);
    float Mc = bred_max(fmaxf(fmaxf(cc[0], cc[1]), fmaxf(cc[2], cc[3])), sm, t);

    float Sa = bred_sum((expf(a[0]-Ma)  + expf(a[1]-Ma))  + (expf(a[2]-Ma)  + expf(a[3]-Ma)),  sm, t);
    float Sb = bred_sum((expf(bb[0]-Mb) + expf(bb[1]-Mb)) + (expf(bb[2]-Mb) + expf(bb[3]-Mb)), sm, t);
    float Sc = bred_sum((expf(cc[0]-Mc) + expf(cc[1]-Mc)) + (expf(cc[2]-Mc) + expf(cc[3]-Mc)), sm, t);

    if (t == 0) {
        g_lse[0*NB + i] = Ma + logf(Sa);
        g_lse[1*NB + i] = Mb + logf(Sb);
        g_lse[2*NB + i] = Mc + logf(Sc);
        __threadfence();
        int v = atomicAdd(&g_ctr, 1);
        isLast = (v == NB - 1);
    }
    __syncthreads();

    if (isLast) {
        float s0 = 0.f, s1 = 0.f, s2 = 0.f;
        #pragma unroll
        for (int r = t; r < NB; r += 128) {
            s0 += g_lse[0*NB + r];
            s1 += g_lse[1*NB + r];
            s2 += g_lse[2*NB + r];
        }
        s0 = bred_sum(s0, sm, t);
        s1 = bred_sum(s1, sm, t);
        s2 = bred_sum(s2, sm, t);
        if (t == 0) {
            g_ctr = 0;
            int v = num_train_p[0];
            float nt;
            if (v > 0 && v < (1 << 30)) nt = (float)v;
            else nt = __int_as_float(v);
            float clogNM = logf(nt * (float)NB);
            float Hf  = -s0 / (float)NB + clogNM;
            float Hz  = -s1 / (float)NB + clogNM;
            float Hfz = -s2 / (float)NB + clogNM;
            float MI  = Hf + Hz - Hfz;
            if (out_size > 0) out[0] = MI;
            if (out_size > 1) out[1] = Hf;
            if (out_size > 2) out[2] = Hz;
            if (out_size > 3) out[3] = Hfz;
        }
    }
}

// ---------------- launch ----------------
extern "C" void kernel_launch(void* const* d_in, const int* in_sizes, int n_in,
                              void* d_out, int out_size) {
    const float* f_mean   = (const float*)d_in[0];
    const float* f_logvar = (const float*)d_in[1];
    const float* f_sample = (const float*)d_in[2];
    const float* z_mean   = (const float*)d_in[3];
    const float* z_logvar = (const float*)d_in[4];
    const float* z_sample = (const float*)d_in[5];
    const int*   num_train = (const int*)d_in[6];

    cudaFuncSetAttribute(gemm_mma_kernel,
                         cudaFuncAttributeMaxDynamicSharedMemorySize, SMEM_DYN);

    prep_kernel<<<dim3(NB, 2), 128>>>(f_mean, f_logvar, f_sample,
                                      z_mean, z_logvar, z_sample);
    gemm_mma_kernel<<<(SPLITF + SPLITZ) * 32, 256, SMEM_DYN>>>();
    lse_kernel<<<NB, 128>>>(num_train, (float*)d_out, out_size);
}